// round 9
// baseline (speedup 1.0000x reference)
#include <cuda_runtime.h>
#include <cuda_bf16.h>
#include <math.h>
#include <stdint.h>

#define VOCAB 32000
#define D 512
#define H 4
#define NLAYER 4
#define B 4
#define S 512
#define HD (H*D)
#define GSPLIT 10
#define BM 128
#define BN 128
#define BK 32
#define PITCH 80
#define MATB 10240           // 128 rows * 80B
#define STG (4*MATB)         // Ah, Al, Bh, Bl per stage
#define SME (3*STG)          // 3-stage pipeline

typedef __nv_bfloat16 bf16;
typedef long long ll;

__device__ __align__(128) float d_e[B*S*D];
__device__ __align__(128) float d_p[(S+1)*D];
__device__ __align__(128) bf16  d_ph[(S+1)*D];
__device__ __align__(128) bf16  d_pl[(S+1)*D];
__device__ __align__(128) float d_mu[D];
__device__ __align__(128) float d_mu_part[128*D];
__device__ __align__(128) bf16  d_Qh[H*S*D];
__device__ __align__(128) bf16  d_Ql[H*S*D];
__device__ __align__(128) bf16  d_Kh[H*S*D];
__device__ __align__(128) bf16  d_Kl[H*S*D];
__device__ __align__(128) bf16  d_wqth[H*D*D];
__device__ __align__(128) bf16  d_wqtl[H*D*D];
__device__ __align__(128) bf16  d_wkth[H*D*D];
__device__ __align__(128) bf16  d_wktl[H*D*D];
__device__ __align__(128) float d_krn[H*S*S];
__device__ __align__(128) bf16  d_krnh[H*S*S];
__device__ __align__(128) bf16  d_krnl[H*S*S];
__device__ __align__(128) float d_fk[B*S*D];
__device__ __align__(128) bf16  d_fkh[B*S*D];
__device__ __align__(128) bf16  d_fkl[B*S*D];
__device__ __align__(128) float d_sc[(size_t)B*S*VOCAB];
__device__ __align__(128) bf16  d_Rh[(size_t)B*S*VOCAB];
__device__ __align__(128) bf16  d_Rl[(size_t)B*S*VOCAB];
__device__ __align__(128) float d_smax[B*VOCAB];
__device__ __align__(128) float d_ssum[B*VOCAB];
__device__ __align__(128) float d_Rsum[B*S];
__device__ __align__(128) float d_part[(size_t)B*GSPLIT*S*D];
__device__ __align__(128) bf16  d_vmh[B*D*S];
__device__ __align__(128) bf16  d_vml[B*D*S];
__device__ __align__(128) bf16  d_Th[(size_t)B*S*HD];
__device__ __align__(128) bf16  d_Tl[(size_t)B*S*HD];
__device__ __align__(128) bf16  d_wh[(size_t)VOCAB*D];
__device__ __align__(128) bf16  d_wl[(size_t)VOCAB*D];
__device__ __align__(128) bf16  d_wth[(size_t)D*VOCAB];
__device__ __align__(128) bf16  d_wtl[(size_t)D*VOCAB];
__device__ __align__(128) bf16  d_woh[D*HD];
__device__ __align__(128) bf16  d_wol[D*HD];
__device__ __align__(128) float d_lnlast[B*D];

__device__ __forceinline__ uint32_t smem_u32(const void* p){
    uint32_t a;
    asm("{ .reg .u64 t; cvta.to.shared.u64 t, %1; cvt.u32.u64 %0, t; }" : "=r"(a) : "l"(p));
    return a;
}
__device__ __forceinline__ void cpa16(uint32_t d, const void* s){
  asm volatile("cp.async.cg.shared.global [%0], [%1], 16;\n" :: "r"(d), "l"(s));
}
#define CP_COMMIT() asm volatile("cp.async.commit_group;\n" ::: "memory")
#define CP_WAIT(n)  asm volatile("cp.async.wait_group %0;\n" :: "n"(n) : "memory")

__device__ __forceinline__ void ldmx4(uint32_t* r, uint32_t a){
  asm volatile("ldmatrix.sync.aligned.m8n8.x4.shared.b16 {%0,%1,%2,%3}, [%4];"
    : "=r"(r[0]),"=r"(r[1]),"=r"(r[2]),"=r"(r[3]) : "r"(a));
}
__device__ __forceinline__ void ldmx2(uint32_t* r, uint32_t a){
  asm volatile("ldmatrix.sync.aligned.m8n8.x2.shared.b16 {%0,%1}, [%2];"
    : "=r"(r[0]),"=r"(r[1]) : "r"(a));
}
__device__ __forceinline__ void mma16816(float* c, const uint32_t* a, const uint32_t* b){
  asm volatile("mma.sync.aligned.m16n8k16.row.col.f32.bf16.bf16.f32 "
    "{%0,%1,%2,%3}, {%4,%5,%6,%7}, {%8,%9}, {%0,%1,%2,%3};"
    : "+f"(c[0]),"+f"(c[1]),"+f"(c[2]),"+f"(c[3])
    : "r"(a[0]),"r"(a[1]),"r"(a[2]),"r"(a[3]), "r"(b[0]),"r"(b[1]));
}
__device__ __forceinline__ void split2(float x, bf16& h, bf16& l){
  h = __float2bfloat16(x);
  l = __float2bfloat16(x - __bfloat162float(h));
}

__device__ __forceinline__ float warpSum(float v){
  #pragma unroll
  for (int o=16;o;o>>=1) v += __shfl_xor_sync(0xffffffffu, v, o);
  return v;
}
__device__ __forceinline__ float warpMax(float v){
  #pragma unroll
  for (int o=16;o;o>>=1) v = fmaxf(v, __shfl_xor_sync(0xffffffffu, v, o));
  return v;
}
template<int NW>
__device__ __forceinline__ float blockSum(float v){
  __shared__ float sm[NW];
  v = warpSum(v);
  int w = threadIdx.x >> 5;
  if ((threadIdx.x & 31) == 0) sm[w] = v;
  __syncthreads();
  float r = (threadIdx.x < NW) ? sm[threadIdx.x] : 0.f;
  r = warpSum(r);
  if (threadIdx.x == 0) sm[0] = r;
  __syncthreads();
  r = sm[0];
  __syncthreads();
  return r;
}
template<int NW>
__device__ __forceinline__ float blockMax(float v){
  __shared__ float sm[NW];
  v = warpMax(v);
  int w = threadIdx.x >> 5;
  if ((threadIdx.x & 31) == 0) sm[w] = v;
  __syncthreads();
  float r = (threadIdx.x < NW) ? sm[threadIdx.x] : -1e30f;
  r = warpMax(r);
  if (threadIdx.x == 0) sm[0] = r;
  __syncthreads();
  r = sm[0];
  __syncthreads();
  return r;
}

// ====== bf16 split-precision NT GEMM via mma.sync, 3-stage cp.async pipeline
// C[M,N] = (Ah+Al)[M,K] @ (Bh+Bl)[N,K]^T, terms AhBh + AhBl + AlBh
// MODE 0: store fp32; MODE 1: accumulate fp32; MODE 2: store bf16 hi/lo split
template<int MODE>
__global__ void __launch_bounds__(256) tgemm(
  const bf16* __restrict__ Ah, const bf16* __restrict__ Al, int lda, ll sAb, ll sAh,
  const bf16* __restrict__ Bh, const bf16* __restrict__ Bl, int ldb, ll sBb, ll sBh,
  float* __restrict__ C, bf16* __restrict__ Chi, bf16* __restrict__ Clo,
  int ldc, ll sCb, ll sCh, ll sCk, int Ktot, int divH, int kSplit)
{
  extern __shared__ char smem[];
  uint32_t sb = smem_u32(smem);
  int tid = threadIdx.x, wid = tid>>5, lane = tid&31;
  int wm = wid>>2, wn = wid&3;           // 2 x 4 warp grid, warp tile 64x32
  int z = blockIdx.z;
  int ks = z % kSplit; z /= kSplit;
  int hh = z % divH;   int bb = z / divH;
  Ah += bb*sAb + hh*sAh;  Al += bb*sAb + hh*sAh;
  Bh += bb*sBb + hh*sBh;  Bl += bb*sBb + hh*sBh;
  ll coff = bb*sCb + hh*sCh + (ll)ks*sCk;
  int kChunk = Ktot / kSplit;
  int k0b = ks * kChunk;
  int m0 = blockIdx.x*BM, n0 = blockIdx.y*BN;

  float acc[4][4][4];
  #pragma unroll
  for (int i=0;i<4;i++)
    #pragma unroll
    for (int j=0;j<4;j++)
      #pragma unroll
      for (int q=0;q<4;q++) acc[i][j][q]=0.f;

  auto ldst = [&](int st, int kc0){
    uint32_t base = sb + (uint32_t)st*STG;
    #pragma unroll
    for (int it=0; it<8; it++){
      int i = tid + it*256;
      int mat = i>>9, j = i&511, r = j>>2, ch = j&3;
      const bf16* src;
      if      (mat==0) src = Ah + (size_t)(m0+r)*lda + kc0 + ch*8;
      else if (mat==1) src = Al + (size_t)(m0+r)*lda + kc0 + ch*8;
      else if (mat==2) src = Bh + (size_t)(n0+r)*ldb + kc0 + ch*8;
      else             src = Bl + (size_t)(n0+r)*ldb + kc0 + ch*8;
      cpa16(base + (uint32_t)mat*MATB + (uint32_t)(r*PITCH + ch*16), src);
    }
    CP_COMMIT();
  };

  int nch = kChunk / BK;
  ldst(0, k0b);
  if (nch > 1) { ldst(1, k0b + BK); CP_WAIT(1); } else { CP_WAIT(0); }
  __syncthreads();

  int lr = lane & 15, lc = lane >> 4;
  int l8 = lane & 7,  l8c = (lane>>3)&1;

  for (int c=0; c<nch; c++){
    int slot = c % 3;
    bool more = (c+2 < nch);
    if (more) ldst((c+2)%3, k0b + (c+2)*BK);   // slot freed two iters ago
    uint32_t base = sb + (uint32_t)slot*STG;
    #pragma unroll
    for (int kk=0; kk<2; kk++){
      uint32_t aH[4][4], aL[4][4], bH[4][2], bL[4][2];
      #pragma unroll
      for (int mi=0; mi<4; mi++){
        uint32_t ra = base + (uint32_t)((wm*64 + mi*16 + lr)*PITCH + (kk*2+lc)*16);
        ldmx4(aH[mi], ra);
        ldmx4(aL[mi], ra + MATB);
      }
      #pragma unroll
      for (int ni=0; ni<4; ni++){
        uint32_t rb = base + 2u*MATB + (uint32_t)((wn*32 + ni*8 + l8)*PITCH + (kk*2+l8c)*16);
        ldmx2(bH[ni], rb);
        ldmx2(bL[ni], rb + MATB);
      }
      #pragma unroll
      for (int mi=0; mi<4; mi++)
        #pragma unroll
        for (int ni=0; ni<4; ni++){
          mma16816(acc[mi][ni], aH[mi], bH[ni]);
          mma16816(acc[mi][ni], aH[mi], bL[ni]);
          mma16816(acc[mi][ni], aL[mi], bH[ni]);
        }
    }
    if (more) { CP_WAIT(1); } else { CP_WAIT(0); }
    __syncthreads();
  }

  int rr = lane>>2, cc = (lane&3)*2;
  #pragma unroll
  for (int mi=0; mi<4; mi++){
    #pragma unroll
    for (int ni=0; ni<4; ni++){
      int r0 = m0 + wm*64 + mi*16 + rr;
      int c0 = n0 + wn*32 + ni*8 + cc;
      float* a = acc[mi][ni];
      if (MODE==0 || MODE==1){
        float* p0 = C + coff + (size_t)r0*ldc + c0;
        float* p1 = C + coff + (size_t)(r0+8)*ldc + c0;
        if (MODE==1){
          float2 o0 = *(float2*)p0, o1 = *(float2*)p1;
          a[0]+=o0.x; a[1]+=o0.y; a[2]+=o1.x; a[3]+=o1.y;
        }
        *(float2*)p0 = make_float2(a[0],a[1]);
        *(float2*)p1 = make_float2(a[2],a[3]);
      } else {
        bf16 h0,l0,h1,l1,h2,l2,h3,l3;
        split2(a[0],h0,l0); split2(a[1],h1,l1);
        split2(a[2],h2,l2); split2(a[3],h3,l3);
        unsigned hp0 = ((unsigned)__bfloat16_as_ushort(h1)<<16) | __bfloat16_as_ushort(h0);
        unsigned lp0 = ((unsigned)__bfloat16_as_ushort(l1)<<16) | __bfloat16_as_ushort(l0);
        unsigned hp1 = ((unsigned)__bfloat16_as_ushort(h3)<<16) | __bfloat16_as_ushort(h2);
        unsigned lp1 = ((unsigned)__bfloat16_as_ushort(l3)<<16) | __bfloat16_as_ushort(l2);
        *(unsigned*)(Chi + coff + (size_t)r0*ldc + c0)     = hp0;
        *(unsigned*)(Clo + coff + (size_t)r0*ldc + c0)     = lp0;
        *(unsigned*)(Chi + coff + (size_t)(r0+8)*ldc + c0) = hp1;
        *(unsigned*)(Clo + coff + (size_t)(r0+8)*ldc + c0) = lp1;
      }
    }
  }
}

// ============ small SIMT kernels ============================================
__global__ void ln_embed(const int* __restrict__ x, const float* __restrict__ wte,
                         const float* __restrict__ g, float* __restrict__ dst){
  int r = blockIdx.x, t = threadIdx.x;
  const float* src = wte + (size_t)x[r]*D;
  float v0 = src[t], v1 = src[t+256];
  float mean = blockSum<8>(v0+v1) * (1.0f/D);
  float a0 = v0-mean, a1 = v1-mean;
  float var = blockSum<8>(a0*a0+a1*a1) * (1.0f/D);
  float inv = rsqrtf(var + 1e-5f);
  dst[(size_t)r*D + t]     = a0*inv*g[t];
  dst[(size_t)r*D + t+256] = a1*inv*g[t+256];
}
__global__ void ln_rows(const float* __restrict__ src0, const float* __restrict__ g,
                        float* __restrict__ dst){
  int r = blockIdx.x, t = threadIdx.x;
  const float* src = src0 + (size_t)r*D;
  float v0 = src[t], v1 = src[t+256];
  float mean = blockSum<8>(v0+v1) * (1.0f/D);
  float a0 = v0-mean, a1 = v1-mean;
  float var = blockSum<8>(a0*a0+a1*a1) * (1.0f/D);
  float inv = rsqrtf(var + 1e-5f);
  dst[(size_t)r*D + t]     = a0*inv*g[t];
  dst[(size_t)r*D + t+256] = a1*inv*g[t+256];
}
__global__ void ln_last(const float* __restrict__ g){
  int b = blockIdx.x, t = threadIdx.x;
  const float* src = d_fk + ((size_t)b*S + (S-1))*D;
  float v0 = src[t], v1 = src[t+256];
  float mean = blockSum<8>(v0+v1) * (1.0f/D);
  float a0 = v0-mean, a1 = v1-mean;
  float var = blockSum<8>(a0*a0+a1*a1) * (1.0f/D);
  float inv = rsqrtf(var + 1e-5f);
  d_lnlast[b*D + t]     = a0*inv*g[t];
  d_lnlast[b*D + t+256] = a1*inv*g[t+256];
}
__global__ void colmean_part(const float* __restrict__ wte){
  int g = blockIdx.x, t = threadIdx.x;
  const float* base = wte + (size_t)g*250*D + t;
  float acc = 0.f;
  for (int r=0; r<250; r++) acc += base[(size_t)r*D];
  d_mu_part[g*D + t] = acc;
}
__global__ void colmean_reduce(){
  int t = threadIdx.x;
  float acc = 0.f;
  for (int g=0; g<128; g++) acc += d_mu_part[g*D + t];
  d_mu[t] = acc * (1.0f/VOCAB);
}
__global__ void wtesplit(const float* __restrict__ wte){
  __shared__ float tile[32][33];
  int d0 = blockIdx.x*32, v0 = blockIdx.y*32;
  int x = threadIdx.x, y = threadIdx.y;
  #pragma unroll
  for (int i=0;i<32;i+=8){
    float val = wte[(size_t)(v0+y+i)*D + d0+x];
    tile[y+i][x] = val;
    bf16 hv, lv; split2(val, hv, lv);
    d_wh[(size_t)(v0+y+i)*D + d0+x] = hv;
    d_wl[(size_t)(v0+y+i)*D + d0+x] = lv;
  }
  __syncthreads();
  #pragma unroll
  for (int i=0;i<32;i+=8){
    float val = tile[x][y+i];
    bf16 hv, lv; split2(val, hv, lv);
    d_wth[(size_t)(d0+y+i)*VOCAB + v0+x] = hv;
    d_wtl[(size_t)(d0+y+i)*VOCAB + v0+x] = lv;
  }
}
// transpose+split per-head weight: out[h][e*D+d] = W[h][d*D+e]
__global__ void wqk_splitT(const float* __restrict__ W, bf16* __restrict__ th, bf16* __restrict__ tl){
  __shared__ float tile[32][33];
  int h = blockIdx.z;
  int d0 = blockIdx.x*32, e0 = blockIdx.y*32;
  const float* src = W + (size_t)h*D*D;
  bf16* oh = th + (size_t)h*D*D;
  bf16* ol = tl + (size_t)h*D*D;
  int x = threadIdx.x, y = threadIdx.y;
  #pragma unroll
  for (int i=0;i<32;i+=8)
    tile[y+i][x] = src[(size_t)(d0+y+i)*D + e0+x];
  __syncthreads();
  #pragma unroll
  for (int i=0;i<32;i+=8){
    float val = tile[x][y+i];
    bf16 hv, lv; split2(val, hv, lv);
    oh[(size_t)(e0+y+i)*D + d0+x] = hv;
    ol[(size_t)(e0+y+i)*D + d0+x] = lv;
  }
}
__global__ void psplit(){
  int i = blockIdx.x*256 + threadIdx.x;
  if (i < (S+1)*D) split2(d_p[i], d_ph[i], d_pl[i]);
}
__global__ void wosplit(const float* __restrict__ Wo){
  int i = blockIdx.x*256 + threadIdx.x;
  split2(Wo[i], d_woh[i], d_wol[i]);
}
__global__ void krnsplit(){
  int i = blockIdx.x*256 + threadIdx.x;
  split2(d_krn[i], d_krnh[i], d_krnl[i]);
}
__global__ void fksplit(){
  int i = blockIdx.x*256 + threadIdx.x;
  split2(d_fk[i], d_fkh[i], d_fkl[i]);
}

__global__ void krn_softmax(){
  int s = blockIdx.x, h = blockIdx.y;
  float* row = d_krn + ((size_t)h*S + s)*S;
  const float scale = 0.044194173824159216f;
  int t0 = threadIdx.x, t1 = threadIdx.x + 256;
  float v0 = fminf(fmaxf(row[t0]*scale, -10.f), 10.f);
  float v1 = fminf(fmaxf(row[t1]*scale, -10.f), 10.f);
  bool ok0 = (t0 <= s), ok1 = (t1 <= s);
  float m0 = ok0 ? v0 : -1e30f;
  float m1 = ok1 ? v1 : -1e30f;
  float mx = blockMax<8>(fmaxf(m0, m1));
  float e0 = ok0 ? __expf(v0-mx) : 0.f;
  float e1 = ok1 ? __expf(v1-mx) : 0.f;
  float sum = blockSum<8>(e0+e1);
  float c = (1.0f/(1.0f+(float)s)) / sum;
  row[t0] = e0*c;
  row[t1] = e1*c;
}
__global__ void smax_pass1(){
  int b = blockIdx.y;
  int v = blockIdx.x*256 + threadIdx.x;
  const float* base = d_sc + (size_t)b*S*VOCAB + v;
  float m = -1e30f, sum = 0.f;
  #pragma unroll 4
  for (int s=0; s<S; s++){
    float x = base[(size_t)s*VOCAB];
    float nm = fmaxf(m, x);
    sum = sum*__expf(m-nm) + __expf(x-nm);
    m = nm;
  }
  d_smax[b*VOCAB+v] = m;
  d_ssum[b*VOCAB+v] = sum;
}
__global__ void smax_pass2(){
  int b = blockIdx.y;
  int v = blockIdx.x*256 + threadIdx.x;
  const float* base = d_sc + (size_t)b*S*VOCAB + v;
  float m = d_smax[b*VOCAB+v];
  float inv = 1.f / d_ssum[b*VOCAB+v];
  bf16* ph = d_Rh + (size_t)b*S*VOCAB + v;
  bf16* pl = d_Rl + (size_t)b*S*VOCAB + v;
  #pragma unroll 4
  for (int s=0; s<S; s++){
    float e = __expf(base[(size_t)s*VOCAB] - m) * inv;
    bf16 hv, lv; split2(e, hv, lv);
    ph[(size_t)s*VOCAB] = hv;
    pl[(size_t)s*VOCAB] = lv;
  }
}
__global__ void rsumT(){
  int r = blockIdx.x;
  const bf16* ph = d_Rh + (size_t)r*VOCAB;
  const bf16* pl = d_Rl + (size_t)r*VOCAB;
  float acc = 0.f;
  for (int v=threadIdx.x; v<VOCAB; v+=256)
    acc += __bfloat162float(ph[v]) + __bfloat162float(pl[v]);
  acc = blockSum<8>(acc);
  if (threadIdx.x==0) d_Rsum[r] = acc;
}
__global__ void vmT(int mode){
  int i = blockIdx.x*256 + threadIdx.x;
  int b = i/(S*D); int rem = i%(S*D);
  int s = rem/D;   int dd = rem%D;
  float ex;
  if (mode){
    float num = 0.f;
    #pragma unroll
    for (int k=0;k<GSPLIT;k++) num += d_part[((size_t)(b*GSPLIT+k))*S*D + rem];
    ex = num / d_Rsum[b*S + s];
  } else {
    ex = d_mu[dd];
  }
  float v = d_e[i] - ex;
  bf16 hv, lv; split2(v, hv, lv);
  d_vmh[(size_t)b*D*S + (size_t)dd*S + s] = hv;
  d_vml[(size_t)b*D*S + (size_t)dd*S + s] = lv;
}
__global__ void logits_kernel(const float* __restrict__ wte, float* __restrict__ out){
  __shared__ float lnv[D];
  int b = blockIdx.x;
  for (int i=threadIdx.x; i<D; i+=256) lnv[i] = d_lnlast[b*D + i];
  __syncthreads();
  int w = threadIdx.x>>5, lane = threadIdx.x & 31;
  int v = blockIdx.y*8 + w;
  const float* wr = wte + (size_t)v*D;
  float acc = 0.f;
  #pragma unroll
  for (int j=lane; j<D; j+=32) acc += wr[j]*lnv[j];
  acc = warpSum(acc);
  if (lane==0) out[(size_t)b*VOCAB + v] = acc;
}

// ============ launch =========================================================
extern "C" void kernel_launch(void* const* d_in, const int* in_sizes, int n_in,
                              void* d_out, int out_size) {
  const int*   x   = (const int*)d_in[0];
  const float* wte = (const float*)d_in[1];
  const float* wpe = (const float*)d_in[2];
  const float* g_e = (const float*)d_in[3];
  const float* g_p = (const float*)d_in[4];
  const float* g_f = (const float*)d_in[5];
  const float* W_q = (const float*)d_in[6];
  const float* W_k = (const float*)d_in[7];
  const float* W_o = (const float*)d_in[8];
  float* out = (float*)d_out;

  cudaFuncSetAttribute(tgemm<0>, cudaFuncAttributeMaxDynamicSharedMemorySize, SME);
  cudaFuncSetAttribute(tgemm<1>, cudaFuncAttributeMaxDynamicSharedMemorySize, SME);
  cudaFuncSetAttribute(tgemm<2>, cudaFuncAttributeMaxDynamicSharedMemorySize, SME);

  float *de, *dp, *dkrn, *dfk, *dsc, *dpart;
  bf16 *dph,*dpl,*dQh,*dQl,*dKh,*dKl,*dwqth,*dwqtl,*dwkth,*dwktl;
  bf16 *dfkh,*dfkl,*dwh,*dwl,*dwth,*dwtl,*dwoh,*dwol,*dkrnh,*dkrnl,*dRh,*dRl,*dvmh,*dvml,*dTh,*dTl;
  cudaGetSymbolAddress((void**)&de,   d_e);
  cudaGetSymbolAddress((void**)&dp,   d_p);
  cudaGetSymbolAddress((void**)&dph,  d_ph);
  cudaGetSymbolAddress((void**)&dpl,  d_pl);
  cudaGetSymbolAddress((void**)&dQh,  d_Qh);
  cudaGetSymbolAddress((void**)&dQl,  d_Ql);
  cudaGetSymbolAddress((void**)&dKh,  d_Kh);
  cudaGetSymbolAddress((void**)&dKl,  d_Kl);
  cudaGetSymbolAddress((void**)&dwqth,d_wqth);
  cudaGetSymbolAddress((void**)&dwqtl,d_wqtl);
  cudaGetSymbolAddress((void**)&dwkth,d_wkth);
  cudaGetSymbolAddress((void**)&dwktl,d_wktl);
  cudaGetSymbolAddress((void**)&dkrn, d_krn);
  cudaGetSymbolAddress((void**)&dfk,  d_fk);
  cudaGetSymbolAddress((void**)&dsc,  d_sc);
  cudaGetSymbolAddress((void**)&dpart,d_part);
  cudaGetSymbolAddress((void**)&dfkh, d_fkh);
  cudaGetSymbolAddress((void**)&dfkl, d_fkl);
  cudaGetSymbolAddress((void**)&dwh,  d_wh);
  cudaGetSymbolAddress((void**)&dwl,  d_wl);
  cudaGetSymbolAddress((void**)&dwth, d_wth);
  cudaGetSymbolAddress((void**)&dwtl, d_wtl);
  cudaGetSymbolAddress((void**)&dwoh, d_woh);
  cudaGetSymbolAddress((void**)&dwol, d_wol);
  cudaGetSymbolAddress((void**)&dkrnh,d_krnh);
  cudaGetSymbolAddress((void**)&dkrnl,d_krnl);
  cudaGetSymbolAddress((void**)&dRh,  d_Rh);
  cudaGetSymbolAddress((void**)&dRl,  d_Rl);
  cudaGetSymbolAddress((void**)&dvmh, d_vmh);
  cudaGetSymbolAddress((void**)&dvml, d_vml);
  cudaGetSymbolAddress((void**)&dTh,  d_Th);
  cudaGetSymbolAddress((void**)&dTl,  d_Tl);

  // setup
  ln_embed<<<B*S, 256>>>(x, wte, g_e, de);
  ln_rows<<<S+1, 256>>>(wpe, g_p, dp);
  psplit<<<((S+1)*D+255)/256, 256>>>();
  colmean_part<<<128, 512>>>(wte);
  colmean_reduce<<<1, 512>>>();
  wtesplit<<<dim3(D/32, VOCAB/32), dim3(32,8)>>>(wte);
  wqk_splitT<<<dim3(D/32, D/32, H), dim3(32,8)>>>(W_q, dwqth, dwqtl);
  wqk_splitT<<<dim3(D/32, D/32, H), dim3(32,8)>>>(W_k, dwkth, dwktl);
  wosplit<<<(D*HD)/256, 256>>>(W_o);

  // Q = x_j @ W_q[h] (NT vs W^T), K = x_i @ W_k[h]; outputs split bf16
  tgemm<2><<<dim3(4,4,H),256,SME>>>(dph+D,dpl+D,D,0,0, dwqth,dwqtl,D,0,(ll)D*D,
                                    0,dQh,dQl,D,0,(ll)S*D,0, D,H,1);
  tgemm<2><<<dim3(4,4,H),256,SME>>>(dph,dpl,D,0,0, dwkth,dwktl,D,0,(ll)D*D,
                                    0,dKh,dKl,D,0,(ll)S*D,0, D,H,1);
  // krn_raw = Q @ K^T
  tgemm<0><<<dim3(4,4,H),256,SME>>>(dQh,dQl,D,0,(ll)S*D, dKh,dKl,D,0,(ll)S*D,
                                    dkrn,0,0,S,0,(ll)S*S,0, D,H,1);
  krn_softmax<<<dim3(S,H),256>>>();
  krnsplit<<<(H*S*S)/256, 256>>>();

  // layer 0: f_k = 0 -> ex = colmean(wte)
  vmT<<<(B*S*D)/256, 256>>>(0);
  tgemm<2><<<dim3(4,4,B*H),256,SME>>>(dkrnh,dkrnl,S,0,(ll)S*S,
                                      dvmh,dvml,S,(ll)D*S,0,
                                      0,dTh,dTl,HD,(ll)S*HD,(ll)D,0, S,H,1);
  tgemm<0><<<dim3(16,4,1),256,SME>>>(dTh,dTl,HD,0,0, dwoh,dwol,HD,0,0,
                                     dfk,0,0,D,0,0,0, HD,1,1);
  fksplit<<<(B*S*D)/256, 256>>>();

  for (int l=1; l<NLAYER; l++){
    tgemm<0><<<dim3(4,250,B),256,SME>>>(dfkh,dfkl,D,(ll)S*D,0,
                                        dwh,dwl,D,0,0,
                                        dsc,0,0,VOCAB,(ll)S*VOCAB,0,0, D,1,1);
    smax_pass1<<<dim3(125,B),256>>>();
    smax_pass2<<<dim3(125,B),256>>>();
    rsumT<<<B*S, 256>>>();
    tgemm<0><<<dim3(4,4,B*GSPLIT),256,SME>>>(dRh,dRl,VOCAB,(ll)S*VOCAB,0,
                                             dwth,dwtl,VOCAB,0,0,
                                             dpart,0,0,D,(ll)GSPLIT*S*D,0,(ll)S*D,
                                             VOCAB,1,GSPLIT);
    vmT<<<(B*S*D)/256, 256>>>(1);
    tgemm<2><<<dim3(4,4,B*H),256,SME>>>(dkrnh,dkrnl,S,0,(ll)S*S,
                                        dvmh,dvml,S,(ll)D*S,0,
                                        0,dTh,dTl,HD,(ll)S*HD,(ll)D,0, S,H,1);
    tgemm<1><<<dim3(16,4,1),256,SME>>>(dTh,dTl,HD,0,0, dwoh,dwol,HD,0,0,
                                       dfk,0,0,D,0,0,0, HD,1,1);
    if (l < NLAYER-1) fksplit<<<(B*S*D)/256, 256>>>();
  }

  ln_last<<<B, 256>>>(g_f);
  logits_kernel<<<dim3(B, VOCAB/8), 256>>>(wte, out);
}

// round 10
// speedup vs baseline: 1.1060x; 1.1060x over previous
#include <cuda_runtime.h>
#include <cuda_bf16.h>
#include <math.h>
#include <stdint.h>

#define VOCAB 32000
#define D 512
#define H 4
#define NLAYER 4
#define B 4
#define S 512
#define HD (H*D)
#define GSPLIT 10
#define BM 128
#define BN 128
#define BK 32
#define PITCH 80
#define MATB 10240           // 128 rows * 80B
#define STG (4*MATB)         // Ah, Al, Bh, Bl per stage
#define SME (2*STG)          // double buffered -> 80KB -> 2 CTAs/SM

typedef __nv_bfloat16 bf16;
typedef long long ll;

__device__ __align__(128) float d_e[B*S*D];
__device__ __align__(128) float d_p[(S+1)*D];
__device__ __align__(128) bf16  d_ph[(S+1)*D];
__device__ __align__(128) bf16  d_pl[(S+1)*D];
__device__ __align__(128) float d_mu[D];
__device__ __align__(128) float d_mu_part[128*D];
__device__ __align__(128) bf16  d_Qh[H*S*D];
__device__ __align__(128) bf16  d_Ql[H*S*D];
__device__ __align__(128) bf16  d_Kh[H*S*D];
__device__ __align__(128) bf16  d_Kl[H*S*D];
__device__ __align__(128) bf16  d_wqth[H*D*D];
__device__ __align__(128) bf16  d_wqtl[H*D*D];
__device__ __align__(128) bf16  d_wkth[H*D*D];
__device__ __align__(128) bf16  d_wktl[H*D*D];
__device__ __align__(128) float d_krn[H*S*S];
__device__ __align__(128) bf16  d_krnh[H*S*S];
__device__ __align__(128) bf16  d_krnl[H*S*S];
__device__ __align__(128) float d_fk[B*S*D];
__device__ __align__(128) bf16  d_fkh[B*S*D];
__device__ __align__(128) bf16  d_fkl[B*S*D];
__device__ __align__(128) float d_sc[(size_t)B*S*VOCAB];
__device__ __align__(128) bf16  d_Rh[(size_t)B*S*VOCAB];
__device__ __align__(128) bf16  d_Rl[(size_t)B*S*VOCAB];
__device__ __align__(128) float d_smax[B*VOCAB];
__device__ __align__(128) float d_ssum[B*VOCAB];
__device__ __align__(128) float d_Rsum[B*S];
__device__ __align__(128) float d_part[(size_t)B*GSPLIT*S*D];
__device__ __align__(128) bf16  d_vmh[B*D*S];
__device__ __align__(128) bf16  d_vml[B*D*S];
__device__ __align__(128) bf16  d_Th[(size_t)B*S*HD];
__device__ __align__(128) bf16  d_Tl[(size_t)B*S*HD];
__device__ __align__(128) bf16  d_wh[(size_t)VOCAB*D];
__device__ __align__(128) bf16  d_wl[(size_t)VOCAB*D];
__device__ __align__(128) bf16  d_wth[(size_t)D*VOCAB];
__device__ __align__(128) bf16  d_wtl[(size_t)D*VOCAB];
__device__ __align__(128) bf16  d_woh[D*HD];
__device__ __align__(128) bf16  d_wol[D*HD];
__device__ __align__(128) float d_lnlast[B*D];

__device__ __forceinline__ uint32_t smem_u32(const void* p){
    uint32_t a;
    asm("{ .reg .u64 t; cvta.to.shared.u64 t, %1; cvt.u32.u64 %0, t; }" : "=r"(a) : "l"(p));
    return a;
}
__device__ __forceinline__ void cpa16(uint32_t d, const void* s){
  asm volatile("cp.async.cg.shared.global [%0], [%1], 16;\n" :: "r"(d), "l"(s));
}
#define CP_COMMIT() asm volatile("cp.async.commit_group;\n" ::: "memory")
#define CP_WAIT(n)  asm volatile("cp.async.wait_group %0;\n" :: "n"(n) : "memory")

__device__ __forceinline__ void ldmx4(uint32_t* r, uint32_t a){
  asm volatile("ldmatrix.sync.aligned.m8n8.x4.shared.b16 {%0,%1,%2,%3}, [%4];"
    : "=r"(r[0]),"=r"(r[1]),"=r"(r[2]),"=r"(r[3]) : "r"(a));
}
__device__ __forceinline__ void ldmx2(uint32_t* r, uint32_t a){
  asm volatile("ldmatrix.sync.aligned.m8n8.x2.shared.b16 {%0,%1}, [%2];"
    : "=r"(r[0]),"=r"(r[1]) : "r"(a));
}
__device__ __forceinline__ void mma16816(float* c, const uint32_t* a, const uint32_t* b){
  asm volatile("mma.sync.aligned.m16n8k16.row.col.f32.bf16.bf16.f32 "
    "{%0,%1,%2,%3}, {%4,%5,%6,%7}, {%8,%9}, {%0,%1,%2,%3};"
    : "+f"(c[0]),"+f"(c[1]),"+f"(c[2]),"+f"(c[3])
    : "r"(a[0]),"r"(a[1]),"r"(a[2]),"r"(a[3]), "r"(b[0]),"r"(b[1]));
}
__device__ __forceinline__ void split2(float x, bf16& h, bf16& l){
  h = __float2bfloat16(x);
  l = __float2bfloat16(x - __bfloat162float(h));
}

__device__ __forceinline__ float warpSum(float v){
  #pragma unroll
  for (int o=16;o;o>>=1) v += __shfl_xor_sync(0xffffffffu, v, o);
  return v;
}
__device__ __forceinline__ float warpMax(float v){
  #pragma unroll
  for (int o=16;o;o>>=1) v = fmaxf(v, __shfl_xor_sync(0xffffffffu, v, o));
  return v;
}
template<int NW>
__device__ __forceinline__ float blockSum(float v){
  __shared__ float sm[NW];
  v = warpSum(v);
  int w = threadIdx.x >> 5;
  if ((threadIdx.x & 31) == 0) sm[w] = v;
  __syncthreads();
  float r = (threadIdx.x < NW) ? sm[threadIdx.x] : 0.f;
  r = warpSum(r);
  if (threadIdx.x == 0) sm[0] = r;
  __syncthreads();
  r = sm[0];
  __syncthreads();
  return r;
}
template<int NW>
__device__ __forceinline__ float blockMax(float v){
  __shared__ float sm[NW];
  v = warpMax(v);
  int w = threadIdx.x >> 5;
  if ((threadIdx.x & 31) == 0) sm[w] = v;
  __syncthreads();
  float r = (threadIdx.x < NW) ? sm[threadIdx.x] : -1e30f;
  r = warpMax(r);
  if (threadIdx.x == 0) sm[0] = r;
  __syncthreads();
  r = sm[0];
  __syncthreads();
  return r;
}

// ====== bf16 split-precision NT GEMM via mma.sync (R8-proven 2-stage pipe)
// C[M,N] = (Ah+Al)[M,K] @ (Bh+Bl)[N,K]^T, terms AhBh + AhBl + AlBh
// MODE 0: store fp32; MODE 1: accumulate fp32; MODE 2: store bf16 hi/lo split
template<int MODE>
__global__ void __launch_bounds__(256) tgemm(
  const bf16* __restrict__ Ah, const bf16* __restrict__ Al, int lda, ll sAb, ll sAh,
  const bf16* __restrict__ Bh, const bf16* __restrict__ Bl, int ldb, ll sBb, ll sBh,
  float* __restrict__ C, bf16* __restrict__ Chi, bf16* __restrict__ Clo,
  int ldc, ll sCb, ll sCh, ll sCk, int Ktot, int divH, int kSplit)
{
  extern __shared__ char smem[];
  uint32_t sb = smem_u32(smem);
  int tid = threadIdx.x, wid = tid>>5, lane = tid&31;
  int wm = wid>>2, wn = wid&3;           // 2 x 4 warp grid, warp tile 64x32
  int z = blockIdx.z;
  int ks = z % kSplit; z /= kSplit;
  int hh = z % divH;   int bb = z / divH;
  Ah += bb*sAb + hh*sAh;  Al += bb*sAb + hh*sAh;
  Bh += bb*sBb + hh*sBh;  Bl += bb*sBb + hh*sBh;
  ll coff = bb*sCb + hh*sCh + (ll)ks*sCk;
  int kChunk = Ktot / kSplit;
  int k0b = ks * kChunk;
  int m0 = blockIdx.x*BM, n0 = blockIdx.y*BN;

  float acc[4][4][4];
  #pragma unroll
  for (int i=0;i<4;i++)
    #pragma unroll
    for (int j=0;j<4;j++)
      #pragma unroll
      for (int q=0;q<4;q++) acc[i][j][q]=0.f;

  auto ldst = [&](int st, int kc0){
    uint32_t base = sb + (uint32_t)st*STG;
    #pragma unroll
    for (int it=0; it<8; it++){
      int i = tid + it*256;
      int mat = i>>9, j = i&511, r = j>>2, ch = j&3;
      const bf16* src;
      if      (mat==0) src = Ah + (size_t)(m0+r)*lda + kc0 + ch*8;
      else if (mat==1) src = Al + (size_t)(m0+r)*lda + kc0 + ch*8;
      else if (mat==2) src = Bh + (size_t)(n0+r)*ldb + kc0 + ch*8;
      else             src = Bl + (size_t)(n0+r)*ldb + kc0 + ch*8;
      cpa16(base + (uint32_t)mat*MATB + (uint32_t)(r*PITCH + ch*16), src);
    }
    CP_COMMIT();
  };

  int nch = kChunk / BK;
  ldst(0, k0b);
  if (nch > 1) ldst(1, k0b + BK);

  int lr = lane & 15, lc = lane >> 4;
  int l8 = lane & 7,  l8c = (lane>>3)&1;

  for (int c=0; c<nch; c++){
    int st = c & 1;
    if (c+1 < nch) { CP_WAIT(1); } else { CP_WAIT(0); }
    __syncthreads();
    uint32_t base = sb + (uint32_t)st*STG;
    #pragma unroll
    for (int kk=0; kk<2; kk++){
      uint32_t aH[4][4], aL[4][4], bH[4][2], bL[4][2];
      #pragma unroll
      for (int mi=0; mi<4; mi++){
        uint32_t ra = base + (uint32_t)((wm*64 + mi*16 + lr)*PITCH + (kk*2+lc)*16);
        ldmx4(aH[mi], ra);
        ldmx4(aL[mi], ra + MATB);
      }
      #pragma unroll
      for (int ni=0; ni<4; ni++){
        uint32_t rb = base + 2u*MATB + (uint32_t)((wn*32 + ni*8 + l8)*PITCH + (kk*2+l8c)*16);
        ldmx2(bH[ni], rb);
        ldmx2(bL[ni], rb + MATB);
      }
      #pragma unroll
      for (int mi=0; mi<4; mi++)
        #pragma unroll
        for (int ni=0; ni<4; ni++){
          mma16816(acc[mi][ni], aH[mi], bH[ni]);
          mma16816(acc[mi][ni], aH[mi], bL[ni]);
          mma16816(acc[mi][ni], aL[mi], bH[ni]);
        }
    }
    __syncthreads();
    if (c+2 < nch) ldst(st, k0b + (c+2)*BK);
  }

  int rr = lane>>2, cc = (lane&3)*2;
  #pragma unroll
  for (int mi=0; mi<4; mi++){
    #pragma unroll
    for (int ni=0; ni<4; ni++){
      int r0 = m0 + wm*64 + mi*16 + rr;
      int c0 = n0 + wn*32 + ni*8 + cc;
      float* a = acc[mi][ni];
      if (MODE==0 || MODE==1){
        float* p0 = C + coff + (size_t)r0*ldc + c0;
        float* p1 = C + coff + (size_t)(r0+8)*ldc + c0;
        if (MODE==1){
          float2 o0 = *(float2*)p0, o1 = *(float2*)p1;
          a[0]+=o0.x; a[1]+=o0.y; a[2]+=o1.x; a[3]+=o1.y;
        }
        *(float2*)p0 = make_float2(a[0],a[1]);
        *(float2*)p1 = make_float2(a[2],a[3]);
      } else {
        bf16 h0,l0,h1,l1,h2,l2,h3,l3;
        split2(a[0],h0,l0); split2(a[1],h1,l1);
        split2(a[2],h2,l2); split2(a[3],h3,l3);
        unsigned hp0 = ((unsigned)__bfloat16_as_ushort(h1)<<16) | __bfloat16_as_ushort(h0);
        unsigned lp0 = ((unsigned)__bfloat16_as_ushort(l1)<<16) | __bfloat16_as_ushort(l0);
        unsigned hp1 = ((unsigned)__bfloat16_as_ushort(h3)<<16) | __bfloat16_as_ushort(h2);
        unsigned lp1 = ((unsigned)__bfloat16_as_ushort(l3)<<16) | __bfloat16_as_ushort(l2);
        *(unsigned*)(Chi + coff + (size_t)r0*ldc + c0)     = hp0;
        *(unsigned*)(Clo + coff + (size_t)r0*ldc + c0)     = lp0;
        *(unsigned*)(Chi + coff + (size_t)(r0+8)*ldc + c0) = hp1;
        *(unsigned*)(Clo + coff + (size_t)(r0+8)*ldc + c0) = lp1;
      }
    }
  }
}

// ============ small SIMT kernels ============================================
__global__ void ln_embed(const int* __restrict__ x, const float* __restrict__ wte,
                         const float* __restrict__ g, float* __restrict__ dst){
  int r = blockIdx.x, t = threadIdx.x;
  const float* src = wte + (size_t)x[r]*D;
  float v0 = src[t], v1 = src[t+256];
  float mean = blockSum<8>(v0+v1) * (1.0f/D);
  float a0 = v0-mean, a1 = v1-mean;
  float var = blockSum<8>(a0*a0+a1*a1) * (1.0f/D);
  float inv = rsqrtf(var + 1e-5f);
  dst[(size_t)r*D + t]     = a0*inv*g[t];
  dst[(size_t)r*D + t+256] = a1*inv*g[t+256];
}
__global__ void ln_rows(const float* __restrict__ src0, const float* __restrict__ g,
                        float* __restrict__ dst){
  int r = blockIdx.x, t = threadIdx.x;
  const float* src = src0 + (size_t)r*D;
  float v0 = src[t], v1 = src[t+256];
  float mean = blockSum<8>(v0+v1) * (1.0f/D);
  float a0 = v0-mean, a1 = v1-mean;
  float var = blockSum<8>(a0*a0+a1*a1) * (1.0f/D);
  float inv = rsqrtf(var + 1e-5f);
  dst[(size_t)r*D + t]     = a0*inv*g[t];
  dst[(size_t)r*D + t+256] = a1*inv*g[t+256];
}
__global__ void ln_last(const float* __restrict__ g){
  int b = blockIdx.x, t = threadIdx.x;
  const float* src = d_fk + ((size_t)b*S + (S-1))*D;
  float v0 = src[t], v1 = src[t+256];
  float mean = blockSum<8>(v0+v1) * (1.0f/D);
  float a0 = v0-mean, a1 = v1-mean;
  float var = blockSum<8>(a0*a0+a1*a1) * (1.0f/D);
  float inv = rsqrtf(var + 1e-5f);
  d_lnlast[b*D + t]     = a0*inv*g[t];
  d_lnlast[b*D + t+256] = a1*inv*g[t+256];
}
__global__ void colmean_part(const float* __restrict__ wte){
  int g = blockIdx.x, t = threadIdx.x;
  const float* base = wte + (size_t)g*250*D + t;
  float acc = 0.f;
  for (int r=0; r<250; r++) acc += base[(size_t)r*D];
  d_mu_part[g*D + t] = acc;
}
__global__ void colmean_reduce(){
  int t = threadIdx.x;
  float acc = 0.f;
  for (int g=0; g<128; g++) acc += d_mu_part[g*D + t];
  d_mu[t] = acc * (1.0f/VOCAB);
}
__global__ void wtesplit(const float* __restrict__ wte){
  __shared__ float tile[32][33];
  int d0 = blockIdx.x*32, v0 = blockIdx.y*32;
  int x = threadIdx.x, y = threadIdx.y;
  #pragma unroll
  for (int i=0;i<32;i+=8){
    float val = wte[(size_t)(v0+y+i)*D + d0+x];
    tile[y+i][x] = val;
    bf16 hv, lv; split2(val, hv, lv);
    d_wh[(size_t)(v0+y+i)*D + d0+x] = hv;
    d_wl[(size_t)(v0+y+i)*D + d0+x] = lv;
  }
  __syncthreads();
  #pragma unroll
  for (int i=0;i<32;i+=8){
    float val = tile[x][y+i];
    bf16 hv, lv; split2(val, hv, lv);
    d_wth[(size_t)(d0+y+i)*VOCAB + v0+x] = hv;
    d_wtl[(size_t)(d0+y+i)*VOCAB + v0+x] = lv;
  }
}
__global__ void wqk_splitT(const float* __restrict__ W, bf16* __restrict__ th, bf16* __restrict__ tl){
  __shared__ float tile[32][33];
  int h = blockIdx.z;
  int d0 = blockIdx.x*32, e0 = blockIdx.y*32;
  const float* src = W + (size_t)h*D*D;
  bf16* oh = th + (size_t)h*D*D;
  bf16* ol = tl + (size_t)h*D*D;
  int x = threadIdx.x, y = threadIdx.y;
  #pragma unroll
  for (int i=0;i<32;i+=8)
    tile[y+i][x] = src[(size_t)(d0+y+i)*D + e0+x];
  __syncthreads();
  #pragma unroll
  for (int i=0;i<32;i+=8){
    float val = tile[x][y+i];
    bf16 hv, lv; split2(val, hv, lv);
    oh[(size_t)(e0+y+i)*D + d0+x] = hv;
    ol[(size_t)(e0+y+i)*D + d0+x] = lv;
  }
}
__global__ void psplit(){
  int i = blockIdx.x*256 + threadIdx.x;
  if (i < (S+1)*D) split2(d_p[i], d_ph[i], d_pl[i]);
}
__global__ void wosplit(const float* __restrict__ Wo){
  int i = blockIdx.x*256 + threadIdx.x;
  split2(Wo[i], d_woh[i], d_wol[i]);
}
__global__ void krnsplit(){
  int i = blockIdx.x*256 + threadIdx.x;
  split2(d_krn[i], d_krnh[i], d_krnl[i]);
}
__global__ void fksplit(){
  int i = blockIdx.x*256 + threadIdx.x;
  split2(d_fk[i], d_fkh[i], d_fkl[i]);
}

__global__ void krn_softmax(){
  int s = blockIdx.x, h = blockIdx.y;
  float* row = d_krn + ((size_t)h*S + s)*S;
  const float scale = 0.044194173824159216f;
  int t0 = threadIdx.x, t1 = threadIdx.x + 256;
  float v0 = fminf(fmaxf(row[t0]*scale, -10.f), 10.f);
  float v1 = fminf(fmaxf(row[t1]*scale, -10.f), 10.f);
  bool ok0 = (t0 <= s), ok1 = (t1 <= s);
  float m0 = ok0 ? v0 : -1e30f;
  float m1 = ok1 ? v1 : -1e30f;
  float mx = blockMax<8>(fmaxf(m0, m1));
  float e0 = ok0 ? __expf(v0-mx) : 0.f;
  float e1 = ok1 ? __expf(v1-mx) : 0.f;
  float sum = blockSum<8>(e0+e1);
  float c = (1.0f/(1.0f+(float)s)) / sum;
  row[t0] = e0*c;
  row[t1] = e1*c;
}
__global__ void smax_pass1(){
  int b = blockIdx.y;
  int v = blockIdx.x*256 + threadIdx.x;
  const float* base = d_sc + (size_t)b*S*VOCAB + v;
  float m = -1e30f, sum = 0.f;
  #pragma unroll 4
  for (int s=0; s<S; s++){
    float x = base[(size_t)s*VOCAB];
    float nm = fmaxf(m, x);
    sum = sum*__expf(m-nm) + __expf(x-nm);
    m = nm;
  }
  d_smax[b*VOCAB+v] = m;
  d_ssum[b*VOCAB+v] = sum;
}
__global__ void smax_pass2(){
  int b = blockIdx.y;
  int v = blockIdx.x*256 + threadIdx.x;
  const float* base = d_sc + (size_t)b*S*VOCAB + v;
  float m = d_smax[b*VOCAB+v];
  float inv = 1.f / d_ssum[b*VOCAB+v];
  bf16* ph = d_Rh + (size_t)b*S*VOCAB + v;
  bf16* pl = d_Rl + (size_t)b*S*VOCAB + v;
  #pragma unroll 4
  for (int s=0; s<S; s++){
    float e = __expf(base[(size_t)s*VOCAB] - m) * inv;
    bf16 hv, lv; split2(e, hv, lv);
    ph[(size_t)s*VOCAB] = hv;
    pl[(size_t)s*VOCAB] = lv;
  }
}
__global__ void rsumT(){
  int r = blockIdx.x;
  const bf16* ph = d_Rh + (size_t)r*VOCAB;
  const bf16* pl = d_Rl + (size_t)r*VOCAB;
  float acc = 0.f;
  for (int v=threadIdx.x; v<VOCAB; v+=256)
    acc += __bfloat162float(ph[v]) + __bfloat162float(pl[v]);
  acc = blockSum<8>(acc);
  if (threadIdx.x==0) d_Rsum[r] = acc;
}
__global__ void vmT(int mode){
  int i = blockIdx.x*256 + threadIdx.x;
  int b = i/(S*D); int rem = i%(S*D);
  int s = rem/D;   int dd = rem%D;
  float ex;
  if (mode){
    float num = 0.f;
    #pragma unroll
    for (int k=0;k<GSPLIT;k++) num += d_part[((size_t)(b*GSPLIT+k))*S*D + rem];
    ex = num / d_Rsum[b*S + s];
  } else {
    ex = d_mu[dd];
  }
  float v = d_e[i] - ex;
  bf16 hv, lv; split2(v, hv, lv);
  d_vmh[(size_t)b*D*S + (size_t)dd*S + s] = hv;
  d_vml[(size_t)b*D*S + (size_t)dd*S + s] = lv;
}
__global__ void logits_kernel(const float* __restrict__ wte, float* __restrict__ out){
  __shared__ float lnv[D];
  int b = blockIdx.x;
  for (int i=threadIdx.x; i<D; i+=256) lnv[i] = d_lnlast[b*D + i];
  __syncthreads();
  int w = threadIdx.x>>5, lane = threadIdx.x & 31;
  int v = blockIdx.y*8 + w;
  const float* wr = wte + (size_t)v*D;
  float acc = 0.f;
  #pragma unroll
  for (int j=lane; j<D; j+=32) acc += wr[j]*lnv[j];
  acc = warpSum(acc);
  if (lane==0) out[(size_t)b*VOCAB + v] = acc;
}

// ============ launch =========================================================
extern "C" void kernel_launch(void* const* d_in, const int* in_sizes, int n_in,
                              void* d_out, int out_size) {
  const int*   x   = (const int*)d_in[0];
  const float* wte = (const float*)d_in[1];
  const float* wpe = (const float*)d_in[2];
  const float* g_e = (const float*)d_in[3];
  const float* g_p = (const float*)d_in[4];
  const float* g_f = (const float*)d_in[5];
  const float* W_q = (const float*)d_in[6];
  const float* W_k = (const float*)d_in[7];
  const float* W_o = (const float*)d_in[8];
  float* out = (float*)d_out;

  cudaFuncSetAttribute(tgemm<0>, cudaFuncAttributeMaxDynamicSharedMemorySize, SME);
  cudaFuncSetAttribute(tgemm<1>, cudaFuncAttributeMaxDynamicSharedMemorySize, SME);
  cudaFuncSetAttribute(tgemm<2>, cudaFuncAttributeMaxDynamicSharedMemorySize, SME);

  float *de, *dp, *dkrn, *dfk, *dsc, *dpart;
  bf16 *dph,*dpl,*dQh,*dQl,*dKh,*dKl,*dwqth,*dwqtl,*dwkth,*dwktl;
  bf16 *dfkh,*dfkl,*dwh,*dwl,*dwth,*dwtl,*dwoh,*dwol,*dkrnh,*dkrnl,*dRh,*dRl,*dvmh,*dvml,*dTh,*dTl;
  cudaGetSymbolAddress((void**)&de,   d_e);
  cudaGetSymbolAddress((void**)&dp,   d_p);
  cudaGetSymbolAddress((void**)&dph,  d_ph);
  cudaGetSymbolAddress((void**)&dpl,  d_pl);
  cudaGetSymbolAddress((void**)&dQh,  d_Qh);
  cudaGetSymbolAddress((void**)&dQl,  d_Ql);
  cudaGetSymbolAddress((void**)&dKh,  d_Kh);
  cudaGetSymbolAddress((void**)&dKl,  d_Kl);
  cudaGetSymbolAddress((void**)&dwqth,d_wqth);
  cudaGetSymbolAddress((void**)&dwqtl,d_wqtl);
  cudaGetSymbolAddress((void**)&dwkth,d_wkth);
  cudaGetSymbolAddress((void**)&dwktl,d_wktl);
  cudaGetSymbolAddress((void**)&dkrn, d_krn);
  cudaGetSymbolAddress((void**)&dfk,  d_fk);
  cudaGetSymbolAddress((void**)&dsc,  d_sc);
  cudaGetSymbolAddress((void**)&dpart,d_part);
  cudaGetSymbolAddress((void**)&dfkh, d_fkh);
  cudaGetSymbolAddress((void**)&dfkl, d_fkl);
  cudaGetSymbolAddress((void**)&dwh,  d_wh);
  cudaGetSymbolAddress((void**)&dwl,  d_wl);
  cudaGetSymbolAddress((void**)&dwth, d_wth);
  cudaGetSymbolAddress((void**)&dwtl, d_wtl);
  cudaGetSymbolAddress((void**)&dwoh, d_woh);
  cudaGetSymbolAddress((void**)&dwol, d_wol);
  cudaGetSymbolAddress((void**)&dkrnh,d_krnh);
  cudaGetSymbolAddress((void**)&dkrnl,d_krnl);
  cudaGetSymbolAddress((void**)&dRh,  d_Rh);
  cudaGetSymbolAddress((void**)&dRl,  d_Rl);
  cudaGetSymbolAddress((void**)&dvmh, d_vmh);
  cudaGetSymbolAddress((void**)&dvml, d_vml);
  cudaGetSymbolAddress((void**)&dTh,  d_Th);
  cudaGetSymbolAddress((void**)&dTl,  d_Tl);

  // setup
  ln_embed<<<B*S, 256>>>(x, wte, g_e, de);
  ln_rows<<<S+1, 256>>>(wpe, g_p, dp);
  psplit<<<((S+1)*D+255)/256, 256>>>();
  colmean_part<<<128, 512>>>(wte);
  colmean_reduce<<<1, 512>>>();
  wtesplit<<<dim3(D/32, VOCAB/32), dim3(32,8)>>>(wte);
  wqk_splitT<<<dim3(D/32, D/32, H), dim3(32,8)>>>(W_q, dwqth, dwqtl);
  wqk_splitT<<<dim3(D/32, D/32, H), dim3(32,8)>>>(W_k, dwkth, dwktl);
  wosplit<<<(D*HD)/256, 256>>>(W_o);

  // Q = x_j @ W_q[h]^T-major, K = x_i @ W_k[h]; outputs split bf16
  tgemm<2><<<dim3(4,4,H),256,SME>>>(dph+D,dpl+D,D,0,0, dwqth,dwqtl,D,0,(ll)D*D,
                                    0,dQh,dQl,D,0,(ll)S*D,0, D,H,1);
  tgemm<2><<<dim3(4,4,H),256,SME>>>(dph,dpl,D,0,0, dwkth,dwktl,D,0,(ll)D*D,
                                    0,dKh,dKl,D,0,(ll)S*D,0, D,H,1);
  // krn_raw = Q @ K^T
  tgemm<0><<<dim3(4,4,H),256,SME>>>(dQh,dQl,D,0,(ll)S*D, dKh,dKl,D,0,(ll)S*D,
                                    dkrn,0,0,S,0,(ll)S*S,0, D,H,1);
  krn_softmax<<<dim3(S,H),256>>>();
  krnsplit<<<(H*S*S)/256, 256>>>();

  // layer 0: f_k = 0 -> ex = colmean(wte)
  vmT<<<(B*S*D)/256, 256>>>(0);
  tgemm<2><<<dim3(4,4,B*H),256,SME>>>(dkrnh,dkrnl,S,0,(ll)S*S,
                                      dvmh,dvml,S,(ll)D*S,0,
                                      0,dTh,dTl,HD,(ll)S*HD,(ll)D,0, S,H,1);
  tgemm<0><<<dim3(16,4,1),256,SME>>>(dTh,dTl,HD,0,0, dwoh,dwol,HD,0,0,
                                     dfk,0,0,D,0,0,0, HD,1,1);
  fksplit<<<(B*S*D)/256, 256>>>();

  for (int l=1; l<NLAYER; l++){
    tgemm<0><<<dim3(4,250,B),256,SME>>>(dfkh,dfkl,D,(ll)S*D,0,
                                        dwh,dwl,D,0,0,
                                        dsc,0,0,VOCAB,(ll)S*VOCAB,0,0, D,1,1);
    smax_pass1<<<dim3(125,B),256>>>();
    smax_pass2<<<dim3(125,B),256>>>();
    rsumT<<<B*S, 256>>>();
    tgemm<0><<<dim3(4,4,B*GSPLIT),256,SME>>>(dRh,dRl,VOCAB,(ll)S*VOCAB,0,
                                             dwth,dwtl,VOCAB,0,0,
                                             dpart,0,0,D,(ll)GSPLIT*S*D,0,(ll)S*D,
                                             VOCAB,1,GSPLIT);
    vmT<<<(B*S*D)/256, 256>>>(1);
    tgemm<2><<<dim3(4,4,B*H),256,SME>>>(dkrnh,dkrnl,S,0,(ll)S*S,
                                        dvmh,dvml,S,(ll)D*S,0,
                                        0,dTh,dTl,HD,(ll)S*HD,(ll)D,0, S,H,1);
    tgemm<1><<<dim3(16,4,1),256,SME>>>(dTh,dTl,HD,0,0, dwoh,dwol,HD,0,0,
                                       dfk,0,0,D,0,0,0, HD,1,1);
    if (l < NLAYER-1) fksplit<<<(B*S*D)/256, 256>>>();
  }

  ln_last<<<B, 256>>>(g_f);
  logits_kernel<<<dim3(B, VOCAB/8), 256>>>(wte, out);
}

// round 12
// speedup vs baseline: 1.5408x; 1.3931x over previous
#include <cuda_runtime.h>
#include <cuda_bf16.h>
#include <math.h>
#include <stdint.h>

#define VOCAB 32000
#define D 512
#define H 4
#define NLAYER 4
#define B 4
#define S 512
#define HD (H*D)
#define GSPLIT 10
#define BM 128
#define BN 128
#define BK 32
#define PITCH 80
#define MATB 10240           // 128 rows * 80B
#define STG (4*MATB)         // Ah, Al, Bh, Bl slots per stage
#define SME (2*STG)          // double buffered -> 80KB -> 2 CTAs/SM

typedef __nv_bfloat16 bf16;
typedef long long ll;

__device__ __align__(128) float d_e[B*S*D];
__device__ __align__(128) float d_p[(S+1)*D];
__device__ __align__(128) bf16  d_ph[(S+1)*D];
__device__ __align__(128) bf16  d_pl[(S+1)*D];
__device__ __align__(128) float d_mu[D];
__device__ __align__(128) float d_mu_part[128*D];
__device__ __align__(128) bf16  d_Qh[H*S*D];
__device__ __align__(128) bf16  d_Ql[H*S*D];
__device__ __align__(128) bf16  d_Kh[H*S*D];
__device__ __align__(128) bf16  d_Kl[H*S*D];
__device__ __align__(128) bf16  d_wqth[H*D*D];
__device__ __align__(128) bf16  d_wqtl[H*D*D];
__device__ __align__(128) bf16  d_wkth[H*D*D];
__device__ __align__(128) bf16  d_wktl[H*D*D];
__device__ __align__(128) float d_krn[H*S*S];
__device__ __align__(128) bf16  d_krnh[H*S*S];
__device__ __align__(128) bf16  d_krnl[H*S*S];
__device__ __align__(128) float d_fk[B*S*D];
__device__ __align__(128) bf16  d_fkh[B*S*D];
__device__ __align__(128) bf16  d_fkl[B*S*D];
__device__ __align__(128) float d_sc[(size_t)B*S*VOCAB];
__device__ __align__(128) bf16  d_Rh[(size_t)B*S*VOCAB];
__device__ __align__(128) float d_smax[B*VOCAB];
__device__ __align__(128) float d_ssum[B*VOCAB];
__device__ __align__(128) float d_Rsum[B*S];
__device__ __align__(128) float d_part[(size_t)B*GSPLIT*S*D];
__device__ __align__(128) bf16  d_vmh[B*D*S];
__device__ __align__(128) bf16  d_vml[B*D*S];
__device__ __align__(128) bf16  d_Th[(size_t)B*S*HD];
__device__ __align__(128) bf16  d_Tl[(size_t)B*S*HD];
__device__ __align__(128) bf16  d_wh[(size_t)VOCAB*D];
__device__ __align__(128) bf16  d_wl[(size_t)VOCAB*D];
__device__ __align__(128) bf16  d_wth[(size_t)D*VOCAB];
__device__ __align__(128) bf16  d_wtl[(size_t)D*VOCAB];
__device__ __align__(128) bf16  d_woh[D*HD];
__device__ __align__(128) bf16  d_wol[D*HD];
__device__ __align__(128) float d_lnlast[B*D];

__device__ __forceinline__ uint32_t smem_u32(const void* p){
    uint32_t a;
    asm("{ .reg .u64 t; cvta.to.shared.u64 t, %1; cvt.u32.u64 %0, t; }" : "=r"(a) : "l"(p));
    return a;
}
__device__ __forceinline__ void cpa16(uint32_t d, const void* s){
  asm volatile("cp.async.cg.shared.global [%0], [%1], 16;\n" :: "r"(d), "l"(s));
}
#define CP_COMMIT() asm volatile("cp.async.commit_group;\n" ::: "memory")
#define CP_WAIT(n)  asm volatile("cp.async.wait_group %0;\n" :: "n"(n) : "memory")

__device__ __forceinline__ void ldmx4(uint32_t* r, uint32_t a){
  asm volatile("ldmatrix.sync.aligned.m8n8.x4.shared.b16 {%0,%1,%2,%3}, [%4];"
    : "=r"(r[0]),"=r"(r[1]),"=r"(r[2]),"=r"(r[3]) : "r"(a));
}
__device__ __forceinline__ void ldmx2(uint32_t* r, uint32_t a){
  asm volatile("ldmatrix.sync.aligned.m8n8.x2.shared.b16 {%0,%1}, [%2];"
    : "=r"(r[0]),"=r"(r[1]) : "r"(a));
}
__device__ __forceinline__ void mma16816(float* c, const uint32_t* a, const uint32_t* b){
  asm volatile("mma.sync.aligned.m16n8k16.row.col.f32.bf16.bf16.f32 "
    "{%0,%1,%2,%3}, {%4,%5,%6,%7}, {%8,%9}, {%0,%1,%2,%3};"
    : "+f"(c[0]),"+f"(c[1]),"+f"(c[2]),"+f"(c[3])
    : "r"(a[0]),"r"(a[1]),"r"(a[2]),"r"(a[3]), "r"(b[0]),"r"(b[1]));
}
__device__ __forceinline__ void split2(float x, bf16& h, bf16& l){
  h = __float2bfloat16(x);
  l = __float2bfloat16(x - __bfloat162float(h));
}

__device__ __forceinline__ float warpSum(float v){
  #pragma unroll
  for (int o=16;o;o>>=1) v += __shfl_xor_sync(0xffffffffu, v, o);
  return v;
}
__device__ __forceinline__ float warpMax(float v){
  #pragma unroll
  for (int o=16;o;o>>=1) v = fmaxf(v, __shfl_xor_sync(0xffffffffu, v, o));
  return v;
}
template<int NW>
__device__ __forceinline__ float blockSum(float v){
  __shared__ float sm[NW];
  v = warpSum(v);
  int w = threadIdx.x >> 5;
  if ((threadIdx.x & 31) == 0) sm[w] = v;
  __syncthreads();
  float r = (threadIdx.x < NW) ? sm[threadIdx.x] : 0.f;
  r = warpSum(r);
  if (threadIdx.x == 0) sm[0] = r;
  __syncthreads();
  r = sm[0];
  __syncthreads();
  return r;
}
template<int NW>
__device__ __forceinline__ float blockMax(float v){
  __shared__ float sm[NW];
  v = warpMax(v);
  int w = threadIdx.x >> 5;
  if ((threadIdx.x & 31) == 0) sm[w] = v;
  __syncthreads();
  float r = (threadIdx.x < NW) ? sm[threadIdx.x] : -1e30f;
  r = warpMax(r);
  if (threadIdx.x == 0) sm[0] = r;
  __syncthreads();
  r = sm[0];
  __syncthreads();
  return r;
}

// ====== bf16 split-precision NT GEMM via mma.sync (2-stage cp.async pipe)
// C[M,N] = A @ B^T with TERMS precision terms:
//   TERMS=3: AhBh + AhBl + AlBh   TERMS=2: AhBh + AlBh (B_lo unused)
//   TERMS=1: AhBh (pure bf16)
// MODE 0: store fp32; MODE 1: accumulate fp32; MODE 2: store bf16 hi/lo split
template<int MODE, int TERMS>
__global__ void __launch_bounds__(256) tgemm(
  const bf16* __restrict__ Ah, const bf16* __restrict__ Al, int lda, ll sAb, ll sAh,
  const bf16* __restrict__ Bh, const bf16* __restrict__ Bl, int ldb, ll sBb, ll sBh,
  float* __restrict__ C, bf16* __restrict__ Chi, bf16* __restrict__ Clo,
  int ldc, ll sCb, ll sCh, ll sCk, int Ktot, int divH, int kSplit)
{
  extern __shared__ char smem[];
  uint32_t sb = smem_u32(smem);
  int tid = threadIdx.x, wid = tid>>5, lane = tid&31;
  int wm = wid>>2, wn = wid&3;           // 2 x 4 warp grid, warp tile 64x32
  int z = blockIdx.z;
  int ks = z % kSplit; z /= kSplit;
  int hh = z % divH;   int bb = z / divH;
  Ah += bb*sAb + hh*sAh;  Al += bb*sAb + hh*sAh;
  Bh += bb*sBb + hh*sBh;  Bl += bb*sBb + hh*sBh;
  ll coff = bb*sCb + hh*sCh + (ll)ks*sCk;
  int kChunk = Ktot / kSplit;
  int k0b = ks * kChunk;
  int m0 = blockIdx.x*BM, n0 = blockIdx.y*BN;

  float acc[4][4][4];
  #pragma unroll
  for (int i=0;i<4;i++)
    #pragma unroll
    for (int j=0;j<4;j++)
      #pragma unroll
      for (int q=0;q<4;q++) acc[i][j][q]=0.f;

  auto ldst = [&](int st, int kc0){
    uint32_t base = sb + (uint32_t)st*STG;
    #pragma unroll
    for (int it=0; it<8; it++){
      int i = tid + it*256;
      int mat = i>>9, j = i&511, r = j>>2, ch = j&3;
      if (mat==1 && TERMS<2) continue;
      if (mat==3 && TERMS<3) continue;
      const bf16* src;
      if      (mat==0) src = Ah + (size_t)(m0+r)*lda + kc0 + ch*8;
      else if (mat==1) src = Al + (size_t)(m0+r)*lda + kc0 + ch*8;
      else if (mat==2) src = Bh + (size_t)(n0+r)*ldb + kc0 + ch*8;
      else             src = Bl + (size_t)(n0+r)*ldb + kc0 + ch*8;
      cpa16(base + (uint32_t)mat*MATB + (uint32_t)(r*PITCH + ch*16), src);
    }
    CP_COMMIT();
  };

  int nch = kChunk / BK;
  ldst(0, k0b);
  if (nch > 1) ldst(1, k0b + BK);

  int lr = lane & 15, lc = lane >> 4;
  int l8 = lane & 7,  l8c = (lane>>3)&1;

  for (int c=0; c<nch; c++){
    int st = c & 1;
    if (c+1 < nch) { CP_WAIT(1); } else { CP_WAIT(0); }
    __syncthreads();
    uint32_t base = sb + (uint32_t)st*STG;
    #pragma unroll
    for (int kk=0; kk<2; kk++){
      uint32_t aH[4][4], aL[4][4], bH[4][2], bL[4][2];
      #pragma unroll
      for (int mi=0; mi<4; mi++){
        uint32_t ra = base + (uint32_t)((wm*64 + mi*16 + lr)*PITCH + (kk*2+lc)*16);
        ldmx4(aH[mi], ra);
        if (TERMS>=2) ldmx4(aL[mi], ra + MATB);
      }
      #pragma unroll
      for (int ni=0; ni<4; ni++){
        uint32_t rb = base + 2u*MATB + (uint32_t)((wn*32 + ni*8 + l8)*PITCH + (kk*2+l8c)*16);
        ldmx2(bH[ni], rb);
        if (TERMS>=3) ldmx2(bL[ni], rb + MATB);
      }
      #pragma unroll
      for (int mi=0; mi<4; mi++)
        #pragma unroll
        for (int ni=0; ni<4; ni++){
          mma16816(acc[mi][ni], aH[mi], bH[ni]);
          if (TERMS>=3) mma16816(acc[mi][ni], aH[mi], bL[ni]);
          if (TERMS>=2) mma16816(acc[mi][ni], aL[mi], bH[ni]);
        }
    }
    __syncthreads();
    if (c+2 < nch) ldst(st, k0b + (c+2)*BK);
  }

  int rr = lane>>2, cc = (lane&3)*2;
  #pragma unroll
  for (int mi=0; mi<4; mi++){
    #pragma unroll
    for (int ni=0; ni<4; ni++){
      int r0 = m0 + wm*64 + mi*16 + rr;
      int c0 = n0 + wn*32 + ni*8 + cc;
      float* a = acc[mi][ni];
      if (MODE==0 || MODE==1){
        float* p0 = C + coff + (size_t)r0*ldc + c0;
        float* p1 = C + coff + (size_t)(r0+8)*ldc + c0;
        if (MODE==1){
          float2 o0 = *(float2*)p0, o1 = *(float2*)p1;
          a[0]+=o0.x; a[1]+=o0.y; a[2]+=o1.x; a[3]+=o1.y;
        }
        *(float2*)p0 = make_float2(a[0],a[1]);
        *(float2*)p1 = make_float2(a[2],a[3]);
      } else {
        bf16 h0,l0,h1,l1,h2,l2,h3,l3;
        split2(a[0],h0,l0); split2(a[1],h1,l1);
        split2(a[2],h2,l2); split2(a[3],h3,l3);
        unsigned hp0 = ((unsigned)__bfloat16_as_ushort(h1)<<16) | __bfloat16_as_ushort(h0);
        unsigned lp0 = ((unsigned)__bfloat16_as_ushort(l1)<<16) | __bfloat16_as_ushort(l0);
        unsigned hp1 = ((unsigned)__bfloat16_as_ushort(h3)<<16) | __bfloat16_as_ushort(h2);
        unsigned lp1 = ((unsigned)__bfloat16_as_ushort(l3)<<16) | __bfloat16_as_ushort(l2);
        *(unsigned*)(Chi + coff + (size_t)r0*ldc + c0)     = hp0;
        *(unsigned*)(Clo + coff + (size_t)r0*ldc + c0)     = lp0;
        *(unsigned*)(Chi + coff + (size_t)(r0+8)*ldc + c0) = hp1;
        *(unsigned*)(Clo + coff + (size_t)(r0+8)*ldc + c0) = lp1;
      }
    }
  }
}

// ============ small SIMT kernels ============================================
__global__ void ln_embed(const int* __restrict__ x, const float* __restrict__ wte,
                         const float* __restrict__ g, float* __restrict__ dst){
  int r = blockIdx.x, t = threadIdx.x;
  const float* src = wte + (size_t)x[r]*D;
  float v0 = src[t], v1 = src[t+256];
  float mean = blockSum<8>(v0+v1) * (1.0f/D);
  float a0 = v0-mean, a1 = v1-mean;
  float var = blockSum<8>(a0*a0+a1*a1) * (1.0f/D);
  float inv = rsqrtf(var + 1e-5f);
  dst[(size_t)r*D + t]     = a0*inv*g[t];
  dst[(size_t)r*D + t+256] = a1*inv*g[t+256];
}
__global__ void ln_rows(const float* __restrict__ src0, const float* __restrict__ g,
                        float* __restrict__ dst){
  int r = blockIdx.x, t = threadIdx.x;
  const float* src = src0 + (size_t)r*D;
  float v0 = src[t], v1 = src[t+256];
  float mean = blockSum<8>(v0+v1) * (1.0f/D);
  float a0 = v0-mean, a1 = v1-mean;
  float var = blockSum<8>(a0*a0+a1*a1) * (1.0f/D);
  float inv = rsqrtf(var + 1e-5f);
  dst[(size_t)r*D + t]     = a0*inv*g[t];
  dst[(size_t)r*D + t+256] = a1*inv*g[t+256];
}
__global__ void ln_last(const float* __restrict__ g){
  int b = blockIdx.x, t = threadIdx.x;
  const float* src = d_fk + ((size_t)b*S + (S-1))*D;
  float v0 = src[t], v1 = src[t+256];
  float mean = blockSum<8>(v0+v1) * (1.0f/D);
  float a0 = v0-mean, a1 = v1-mean;
  float var = blockSum<8>(a0*a0+a1*a1) * (1.0f/D);
  float inv = rsqrtf(var + 1e-5f);
  d_lnlast[b*D + t]     = a0*inv*g[t];
  d_lnlast[b*D + t+256] = a1*inv*g[t+256];
}
__global__ void colmean_part(const float* __restrict__ wte){
  int g = blockIdx.x, t = threadIdx.x;
  const float* base = wte + (size_t)g*250*D + t;
  float acc = 0.f;
  for (int r=0; r<250; r++) acc += base[(size_t)r*D];
  d_mu_part[g*D + t] = acc;
}
__global__ void colmean_reduce(){
  int t = threadIdx.x;
  float acc = 0.f;
  for (int g=0; g<128; g++) acc += d_mu_part[g*D + t];
  d_mu[t] = acc * (1.0f/VOCAB);
}
__global__ void wtesplit(const float* __restrict__ wte){
  __shared__ float tile[32][33];
  int d0 = blockIdx.x*32, v0 = blockIdx.y*32;
  int x = threadIdx.x, y = threadIdx.y;
  #pragma unroll
  for (int i=0;i<32;i+=8){
    float val = wte[(size_t)(v0+y+i)*D + d0+x];
    tile[y+i][x] = val;
    bf16 hv, lv; split2(val, hv, lv);
    d_wh[(size_t)(v0+y+i)*D + d0+x] = hv;
    d_wl[(size_t)(v0+y+i)*D + d0+x] = lv;
  }
  __syncthreads();
  #pragma unroll
  for (int i=0;i<32;i+=8){
    float val = tile[x][y+i];
    bf16 hv, lv; split2(val, hv, lv);
    d_wth[(size_t)(d0+y+i)*VOCAB + v0+x] = hv;
    d_wtl[(size_t)(d0+y+i)*VOCAB + v0+x] = lv;
  }
}
__global__ void wqk_splitT(const float* __restrict__ W, bf16* __restrict__ th, bf16* __restrict__ tl){
  __shared__ float tile[32][33];
  int h = blockIdx.z;
  int d0 = blockIdx.x*32, e0 = blockIdx.y*32;
  const float* src = W + (size_t)h*D*D;
  bf16* oh = th + (size_t)h*D*D;
  bf16* ol = tl + (size_t)h*D*D;
  int x = threadIdx.x, y = threadIdx.y;
  #pragma unroll
  for (int i=0;i<32;i+=8)
    tile[y+i][x] = src[(size_t)(d0+y+i)*D + e0+x];
  __syncthreads();
  #pragma unroll
  for (int i=0;i<32;i+=8){
    float val = tile[x][y+i];
    bf16 hv, lv; split2(val, hv, lv);
    oh[(size_t)(e0+y+i)*D + d0+x] = hv;
    ol[(size_t)(e0+y+i)*D + d0+x] = lv;
  }
}
__global__ void psplit(){
  int i = blockIdx.x*256 + threadIdx.x;
  if (i < (S+1)*D) split2(d_p[i], d_ph[i], d_pl[i]);
}
__global__ void wosplit(const float* __restrict__ Wo){
  int i = blockIdx.x*256 + threadIdx.x;
  split2(Wo[i], d_woh[i], d_wol[i]);
}
__global__ void krnsplit(){
  int i = blockIdx.x*256 + threadIdx.x;
  split2(d_krn[i], d_krnh[i], d_krnl[i]);
}
__global__ void fksplit(){
  int i = blockIdx.x*256 + threadIdx.x;
  split2(d_fk[i], d_fkh[i], d_fkl[i]);
}

__global__ void krn_softmax(){
  int s = blockIdx.x, h = blockIdx.y;
  float* row = d_krn + ((size_t)h*S + s)*S;
  const float scale = 0.044194173824159216f;
  int t0 = threadIdx.x, t1 = threadIdx.x + 256;
  float v0 = fminf(fmaxf(row[t0]*scale, -10.f), 10.f);
  float v1 = fminf(fmaxf(row[t1]*scale, -10.f), 10.f);
  bool ok0 = (t0 <= s), ok1 = (t1 <= s);
  float m0 = ok0 ? v0 : -1e30f;
  float m1 = ok1 ? v1 : -1e30f;
  float mx = blockMax<8>(fmaxf(m0, m1));
  float e0 = ok0 ? __expf(v0-mx) : 0.f;
  float e1 = ok1 ? __expf(v1-mx) : 0.f;
  float sum = blockSum<8>(e0+e1);
  float c = (1.0f/(1.0f+(float)s)) / sum;
  row[t0] = e0*c;
  row[t1] = e1*c;
}
__global__ void smax_pass1(){
  int b = blockIdx.y;
  int v = blockIdx.x*256 + threadIdx.x;
  const float* base = d_sc + (size_t)b*S*VOCAB + v;
  float m = -1e30f, sum = 0.f;
  #pragma unroll 4
  for (int s=0; s<S; s++){
    float x = base[(size_t)s*VOCAB];
    float nm = fmaxf(m, x);
    sum = sum*__expf(m-nm) + __expf(x-nm);
    m = nm;
  }
  d_smax[b*VOCAB+v] = m;
  d_ssum[b*VOCAB+v] = sum;
}
__global__ void smax_pass2(){
  int b = blockIdx.y;
  int v = blockIdx.x*256 + threadIdx.x;
  const float* base = d_sc + (size_t)b*S*VOCAB + v;
  float m = d_smax[b*VOCAB+v];
  float inv = 1.f / d_ssum[b*VOCAB+v];
  bf16* ph = d_Rh + (size_t)b*S*VOCAB + v;
  #pragma unroll 4
  for (int s=0; s<S; s++){
    float e = __expf(base[(size_t)s*VOCAB] - m) * inv;
    ph[(size_t)s*VOCAB] = __float2bfloat16(e);
  }
}
__global__ void rsumT(){
  int r = blockIdx.x;
  const bf16* ph = d_Rh + (size_t)r*VOCAB;
  float acc = 0.f;
  for (int v=threadIdx.x; v<VOCAB; v+=256)
    acc += __bfloat162float(ph[v]);
  acc = blockSum<8>(acc);
  if (threadIdx.x==0) d_Rsum[r] = acc;
}
__global__ void vmT(int mode){
  int i = blockIdx.x*256 + threadIdx.x;
  int b = i/(S*D); int rem = i%(S*D);
  int s = rem/D;   int dd = rem%D;
  float ex;
  if (mode){
    float num = 0.f;
    #pragma unroll
    for (int k=0;k<GSPLIT;k++) num += d_part[((size_t)(b*GSPLIT+k))*S*D + rem];
    ex = num / d_Rsum[b*S + s];
  } else {
    ex = d_mu[dd];
  }
  float v = d_e[i] - ex;
  bf16 hv, lv; split2(v, hv, lv);
  d_vmh[(size_t)b*D*S + (size_t)dd*S + s] = hv;
  d_vml[(size_t)b*D*S + (size_t)dd*S + s] = lv;
}
__global__ void logits_kernel(const float* __restrict__ wte, float* __restrict__ out){
  __shared__ float lnv[D];
  int b = blockIdx.x;
  for (int i=threadIdx.x; i<D; i+=256) lnv[i] = d_lnlast[b*D + i];
  __syncthreads();
  int w = threadIdx.x>>5, lane = threadIdx.x & 31;
  int v = blockIdx.y*8 + w;
  const float* wr = wte + (size_t)v*D;
  float acc = 0.f;
  #pragma unroll
  for (int j=lane; j<D; j+=32) acc += wr[j]*lnv[j];
  acc = warpSum(acc);
  if (lane==0) out[(size_t)b*VOCAB + v] = acc;
}

// ============ launch =========================================================
extern "C" void kernel_launch(void* const* d_in, const int* in_sizes, int n_in,
                              void* d_out, int out_size) {
  const int*   x   = (const int*)d_in[0];
  const float* wte = (const float*)d_in[1];
  const float* wpe = (const float*)d_in[2];
  const float* g_e = (const float*)d_in[3];
  const float* g_p = (const float*)d_in[4];
  const float* g_f = (const float*)d_in[5];
  const float* W_q = (const float*)d_in[6];
  const float* W_k = (const float*)d_in[7];
  const float* W_o = (const float*)d_in[8];
  float* out = (float*)d_out;

  cudaFuncSetAttribute(tgemm<0,3>, cudaFuncAttributeMaxDynamicSharedMemorySize, SME);
  cudaFuncSetAttribute(tgemm<1,3>, cudaFuncAttributeMaxDynamicSharedMemorySize, SME);
  cudaFuncSetAttribute(tgemm<2,3>, cudaFuncAttributeMaxDynamicSharedMemorySize, SME);
  cudaFuncSetAttribute(tgemm<0,2>, cudaFuncAttributeMaxDynamicSharedMemorySize, SME);
  cudaFuncSetAttribute(tgemm<0,1>, cudaFuncAttributeMaxDynamicSharedMemorySize, SME);

  float *de, *dp, *dkrn, *dfk, *dsc, *dpart;
  bf16 *dph,*dpl,*dQh,*dQl,*dKh,*dKl,*dwqth,*dwqtl,*dwkth,*dwktl;
  bf16 *dfkh,*dfkl,*dwh,*dwl,*dwth,*dwtl,*dwoh,*dwol,*dkrnh,*dkrnl,*dRh,*dvmh,*dvml,*dTh,*dTl;
  cudaGetSymbolAddress((void**)&de,   d_e);
  cudaGetSymbolAddress((void**)&dp,   d_p);
  cudaGetSymbolAddress((void**)&dph,  d_ph);
  cudaGetSymbolAddress((void**)&dpl,  d_pl);
  cudaGetSymbolAddress((void**)&dQh,  d_Qh);
  cudaGetSymbolAddress((void**)&dQl,  d_Ql);
  cudaGetSymbolAddress((void**)&dKh,  d_Kh);
  cudaGetSymbolAddress((void**)&dKl,  d_Kl);
  cudaGetSymbolAddress((void**)&dwqth,d_wqth);
  cudaGetSymbolAddress((void**)&dwqtl,d_wqtl);
  cudaGetSymbolAddress((void**)&dwkth,d_wkth);
  cudaGetSymbolAddress((void**)&dwktl,d_wktl);
  cudaGetSymbolAddress((void**)&dkrn, d_krn);
  cudaGetSymbolAddress((void**)&dfk,  d_fk);
  cudaGetSymbolAddress((void**)&dsc,  d_sc);
  cudaGetSymbolAddress((void**)&dpart,d_part);
  cudaGetSymbolAddress((void**)&dfkh, d_fkh);
  cudaGetSymbolAddress((void**)&dfkl, d_fkl);
  cudaGetSymbolAddress((void**)&dwh,  d_wh);
  cudaGetSymbolAddress((void**)&dwl,  d_wl);
  cudaGetSymbolAddress((void**)&dwth, d_wth);
  cudaGetSymbolAddress((void**)&dwtl, d_wtl);
  cudaGetSymbolAddress((void**)&dwoh, d_woh);
  cudaGetSymbolAddress((void**)&dwol, d_wol);
  cudaGetSymbolAddress((void**)&dkrnh,d_krnh);
  cudaGetSymbolAddress((void**)&dkrnl,d_krnl);
  cudaGetSymbolAddress((void**)&dRh,  d_Rh);
  cudaGetSymbolAddress((void**)&dvmh, d_vmh);
  cudaGetSymbolAddress((void**)&dvml, d_vml);
  cudaGetSymbolAddress((void**)&dTh,  d_Th);
  cudaGetSymbolAddress((void**)&dTl,  d_Tl);

  // setup
  ln_embed<<<B*S, 256>>>(x, wte, g_e, de);
  ln_rows<<<S+1, 256>>>(wpe, g_p, dp);
  psplit<<<((S+1)*D+255)/256, 256>>>();
  colmean_part<<<128, 512>>>(wte);
  colmean_reduce<<<1, 512>>>();
  wtesplit<<<dim3(D/32, VOCAB/32), dim3(32,8)>>>(wte);
  wqk_splitT<<<dim3(D/32, D/32, H), dim3(32,8)>>>(W_q, dwqth, dwqtl);
  wqk_splitT<<<dim3(D/32, D/32, H), dim3(32,8)>>>(W_k, dwkth, dwktl);
  wosplit<<<(D*HD)/256, 256>>>(W_o);

  // Q = x_j @ W_q[h], K = x_i @ W_k[h]; outputs split bf16 (full precision)
  tgemm<2,3><<<dim3(4,4,H),256,SME>>>(dph+D,dpl+D,D,0,0, dwqth,dwqtl,D,0,(ll)D*D,
                                      0,dQh,dQl,D,0,(ll)S*D,0, D,H,1);
  tgemm<2,3><<<dim3(4,4,H),256,SME>>>(dph,dpl,D,0,0, dwkth,dwktl,D,0,(ll)D*D,
                                      0,dKh,dKl,D,0,(ll)S*D,0, D,H,1);
  // krn_raw = Q @ K^T (full precision)
  tgemm<0,3><<<dim3(4,4,H),256,SME>>>(dQh,dQl,D,0,(ll)S*D, dKh,dKl,D,0,(ll)S*D,
                                      dkrn,0,0,S,0,(ll)S*S,0, D,H,1);
  krn_softmax<<<dim3(S,H),256>>>();
  krnsplit<<<(H*S*S)/256, 256>>>();

  // layer 0: f_k = 0 -> ex = colmean(wte)
  vmT<<<(B*S*D)/256, 256>>>(0);
  tgemm<2,3><<<dim3(4,4,B*H),256,SME>>>(dkrnh,dkrnl,S,0,(ll)S*S,
                                        dvmh,dvml,S,(ll)D*S,0,
                                        0,dTh,dTl,HD,(ll)S*HD,(ll)D,0, S,H,1);
  tgemm<0,3><<<dim3(16,4,1),256,SME>>>(dTh,dTl,HD,0,0, dwoh,dwol,HD,0,0,
                                       dfk,0,0,D,0,0,0, HD,1,1);
  fksplit<<<(B*S*D)/256, 256>>>();

  for (int l=1; l<NLAYER; l++){
    // scoresT = fk @ wte^T : 2-term (wte_lo dropped; softmax-averaged downstream)
    tgemm<0,2><<<dim3(4,250,B),256,SME>>>(dfkh,dfkl,D,(ll)S*D,0,
                                          dwh,dwl,D,0,0,
                                          dsc,0,0,VOCAB,(ll)S*VOCAB,0,0, D,1,1);
    smax_pass1<<<dim3(125,B),256>>>();
    smax_pass2<<<dim3(125,B),256>>>();
    rsumT<<<B*S, 256>>>();
    // num = R_hi @ wte : 1-term (ex is subtracted from O(1) embedding; error ~1e-4)
    tgemm<0,1><<<dim3(4,4,B*GSPLIT),256,SME>>>(dRh,dRh,VOCAB,(ll)S*VOCAB,0,
                                               dwth,dwtl,VOCAB,0,0,
                                               dpart,0,0,D,(ll)GSPLIT*S*D,0,(ll)S*D,
                                               VOCAB,1,GSPLIT);
    vmT<<<(B*S*D)/256, 256>>>(1);
    tgemm<2,3><<<dim3(4,4,B*H),256,SME>>>(dkrnh,dkrnl,S,0,(ll)S*S,
                                          dvmh,dvml,S,(ll)D*S,0,
                                          0,dTh,dTl,HD,(ll)S*HD,(ll)D,0, S,H,1);
    tgemm<1,3><<<dim3(16,4,1),256,SME>>>(dTh,dTl,HD,0,0, dwoh,dwol,HD,0,0,
                                         dfk,0,0,D,0,0,0, HD,1,1);
    if (l < NLAYER-1) fksplit<<<(B*S*D)/256, 256>>>();
  }

  ln_last<<<B, 256>>>(g_f);
  logits_kernel<<<dim3(B, VOCAB/8), 256>>>(wte, out);
}

// round 13
// speedup vs baseline: 1.6249x; 1.0546x over previous
#include <cuda_runtime.h>
#include <cuda_bf16.h>
#include <math.h>
#include <stdint.h>

#define VOCAB 32000
#define D 512
#define H 4
#define NLAYER 4
#define B 4
#define S 512
#define HD (H*D)
#define GSPLIT 10
#define WOK 4
#define BM 128
#define BN 128
#define BK 32
#define PITCH 80
#define MATB 10240           // 128 rows * 80B
#define STG (4*MATB)         // Ah, Al, Bh, Bl slots per stage
#define SME (2*STG)          // double buffered -> 80KB -> 2 CTAs/SM

typedef __nv_bfloat16 bf16;
typedef long long ll;

__device__ __align__(128) float d_e[B*S*D];
__device__ __align__(128) float d_p[(S+1)*D];
__device__ __align__(128) bf16  d_ph[(S+1)*D];
__device__ __align__(128) bf16  d_pl[(S+1)*D];
__device__ __align__(128) float d_mu[D];
__device__ __align__(128) float d_mu_part[128*D];
__device__ __align__(128) bf16  d_Qh[H*S*D];
__device__ __align__(128) bf16  d_Ql[H*S*D];
__device__ __align__(128) bf16  d_Kh[H*S*D];
__device__ __align__(128) bf16  d_Kl[H*S*D];
__device__ __align__(128) bf16  d_wqth[H*D*D];
__device__ __align__(128) bf16  d_wqtl[H*D*D];
__device__ __align__(128) bf16  d_wkth[H*D*D];
__device__ __align__(128) bf16  d_wktl[H*D*D];
__device__ __align__(128) float d_krn[H*S*S];
__device__ __align__(128) bf16  d_krnh[H*S*S];
__device__ __align__(128) bf16  d_krnl[H*S*S];
__device__ __align__(128) float d_fk[B*S*D];
__device__ __align__(128) bf16  d_fkh[B*S*D];
__device__ __align__(128) bf16  d_fkl[B*S*D];
__device__ __align__(128) bf16  d_sch[(size_t)B*S*VOCAB];   // scoresT bf16
__device__ __align__(128) bf16  d_Rh[(size_t)B*S*VOCAB];
__device__ __align__(128) float d_smax[B*VOCAB];
__device__ __align__(128) float d_ssum[B*VOCAB];
__device__ __align__(128) float d_Rsum[B*S];
__device__ __align__(128) float d_part[(size_t)B*GSPLIT*S*D];
__device__ __align__(128) bf16  d_vmh[B*D*S];
__device__ __align__(128) bf16  d_vml[B*D*S];
__device__ __align__(128) bf16  d_Th[(size_t)B*S*HD];
__device__ __align__(128) bf16  d_Tl[(size_t)B*S*HD];
__device__ __align__(128) bf16  d_wh[(size_t)VOCAB*D];
__device__ __align__(128) bf16  d_wl[(size_t)VOCAB*D];
__device__ __align__(128) bf16  d_wth[(size_t)D*VOCAB];
__device__ __align__(128) bf16  d_wtl[(size_t)D*VOCAB];
__device__ __align__(128) bf16  d_woh[D*HD];
__device__ __align__(128) bf16  d_wol[D*HD];
__device__ __align__(128) float d_lnlast[B*D];

__device__ __forceinline__ uint32_t smem_u32(const void* p){
    uint32_t a;
    asm("{ .reg .u64 t; cvta.to.shared.u64 t, %1; cvt.u32.u64 %0, t; }" : "=r"(a) : "l"(p));
    return a;
}
__device__ __forceinline__ void cpa16(uint32_t d, const void* s){
  asm volatile("cp.async.cg.shared.global [%0], [%1], 16;\n" :: "r"(d), "l"(s));
}
#define CP_COMMIT() asm volatile("cp.async.commit_group;\n" ::: "memory")
#define CP_WAIT(n)  asm volatile("cp.async.wait_group %0;\n" :: "n"(n) : "memory")

__device__ __forceinline__ void ldmx4(uint32_t* r, uint32_t a){
  asm volatile("ldmatrix.sync.aligned.m8n8.x4.shared.b16 {%0,%1,%2,%3}, [%4];"
    : "=r"(r[0]),"=r"(r[1]),"=r"(r[2]),"=r"(r[3]) : "r"(a));
}
__device__ __forceinline__ void ldmx2(uint32_t* r, uint32_t a){
  asm volatile("ldmatrix.sync.aligned.m8n8.x2.shared.b16 {%0,%1}, [%2];"
    : "=r"(r[0]),"=r"(r[1]) : "r"(a));
}
__device__ __forceinline__ void mma16816(float* c, const uint32_t* a, const uint32_t* b){
  asm volatile("mma.sync.aligned.m16n8k16.row.col.f32.bf16.bf16.f32 "
    "{%0,%1,%2,%3}, {%4,%5,%6,%7}, {%8,%9}, {%0,%1,%2,%3};"
    : "+f"(c[0]),"+f"(c[1]),"+f"(c[2]),"+f"(c[3])
    : "r"(a[0]),"r"(a[1]),"r"(a[2]),"r"(a[3]), "r"(b[0]),"r"(b[1]));
}
__device__ __forceinline__ void split2(float x, bf16& h, bf16& l){
  h = __float2bfloat16(x);
  l = __float2bfloat16(x - __bfloat162float(h));
}

__device__ __forceinline__ float warpSum(float v){
  #pragma unroll
  for (int o=16;o;o>>=1) v += __shfl_xor_sync(0xffffffffu, v, o);
  return v;
}
__device__ __forceinline__ float warpMax(float v){
  #pragma unroll
  for (int o=16;o;o>>=1) v = fmaxf(v, __shfl_xor_sync(0xffffffffu, v, o));
  return v;
}
template<int NW>
__device__ __forceinline__ float blockSum(float v){
  __shared__ float sm[NW];
  v = warpSum(v);
  int w = threadIdx.x >> 5;
  if ((threadIdx.x & 31) == 0) sm[w] = v;
  __syncthreads();
  float r = (threadIdx.x < NW) ? sm[threadIdx.x] : 0.f;
  r = warpSum(r);
  if (threadIdx.x == 0) sm[0] = r;
  __syncthreads();
  r = sm[0];
  __syncthreads();
  return r;
}
template<int NW>
__device__ __forceinline__ float blockMax(float v){
  __shared__ float sm[NW];
  v = warpMax(v);
  int w = threadIdx.x >> 5;
  if ((threadIdx.x & 31) == 0) sm[w] = v;
  __syncthreads();
  float r = (threadIdx.x < NW) ? sm[threadIdx.x] : -1e30f;
  r = warpMax(r);
  if (threadIdx.x == 0) sm[0] = r;
  __syncthreads();
  r = sm[0];
  __syncthreads();
  return r;
}

// ====== bf16 split-precision NT GEMM via mma.sync (2-stage cp.async pipe)
// TERMS=3: AhBh+AhBl+AlBh  TERMS=2: AhBh+AlBh  TERMS=1: AhBh
// MODE 0: store fp32; 1: accumulate fp32; 2: store bf16 hi/lo; 3: store bf16 hi
template<int MODE, int TERMS>
__global__ void __launch_bounds__(256) tgemm(
  const bf16* __restrict__ Ah, const bf16* __restrict__ Al, int lda, ll sAb, ll sAh,
  const bf16* __restrict__ Bh, const bf16* __restrict__ Bl, int ldb, ll sBb, ll sBh,
  float* __restrict__ C, bf16* __restrict__ Chi, bf16* __restrict__ Clo,
  int ldc, ll sCb, ll sCh, ll sCk, int Ktot, int divH, int kSplit)
{
  extern __shared__ char smem[];
  uint32_t sb = smem_u32(smem);
  int tid = threadIdx.x, wid = tid>>5, lane = tid&31;
  int wm = wid>>2, wn = wid&3;           // 2 x 4 warp grid, warp tile 64x32
  int z = blockIdx.z;
  int ks = z % kSplit; z /= kSplit;
  int hh = z % divH;   int bb = z / divH;
  Ah += bb*sAb + hh*sAh;  Al += bb*sAb + hh*sAh;
  Bh += bb*sBb + hh*sBh;  Bl += bb*sBb + hh*sBh;
  ll coff = bb*sCb + hh*sCh + (ll)ks*sCk;
  int kChunk = Ktot / kSplit;
  int k0b = ks * kChunk;
  int m0 = blockIdx.x*BM, n0 = blockIdx.y*BN;

  float acc[4][4][4];
  #pragma unroll
  for (int i=0;i<4;i++)
    #pragma unroll
    for (int j=0;j<4;j++)
      #pragma unroll
      for (int q=0;q<4;q++) acc[i][j][q]=0.f;

  auto ldst = [&](int st, int kc0){
    uint32_t base = sb + (uint32_t)st*STG;
    #pragma unroll
    for (int it=0; it<8; it++){
      int i = tid + it*256;
      int mat = i>>9, j = i&511, r = j>>2, ch = j&3;
      if (mat==1 && TERMS<2) continue;
      if (mat==3 && TERMS<3) continue;
      const bf16* src;
      if      (mat==0) src = Ah + (size_t)(m0+r)*lda + kc0 + ch*8;
      else if (mat==1) src = Al + (size_t)(m0+r)*lda + kc0 + ch*8;
      else if (mat==2) src = Bh + (size_t)(n0+r)*ldb + kc0 + ch*8;
      else             src = Bl + (size_t)(n0+r)*ldb + kc0 + ch*8;
      cpa16(base + (uint32_t)mat*MATB + (uint32_t)(r*PITCH + ch*16), src);
    }
    CP_COMMIT();
  };

  int nch = kChunk / BK;
  ldst(0, k0b);
  if (nch > 1) ldst(1, k0b + BK);

  int lr = lane & 15, lc = lane >> 4;
  int l8 = lane & 7,  l8c = (lane>>3)&1;

  for (int c=0; c<nch; c++){
    int st = c & 1;
    if (c+1 < nch) { CP_WAIT(1); } else { CP_WAIT(0); }
    __syncthreads();
    uint32_t base = sb + (uint32_t)st*STG;
    #pragma unroll
    for (int kk=0; kk<2; kk++){
      uint32_t aH[4][4], aL[4][4], bH[4][2], bL[4][2];
      #pragma unroll
      for (int mi=0; mi<4; mi++){
        uint32_t ra = base + (uint32_t)((wm*64 + mi*16 + lr)*PITCH + (kk*2+lc)*16);
        ldmx4(aH[mi], ra);
        if (TERMS>=2) ldmx4(aL[mi], ra + MATB);
      }
      #pragma unroll
      for (int ni=0; ni<4; ni++){
        uint32_t rb = base + 2u*MATB + (uint32_t)((wn*32 + ni*8 + l8)*PITCH + (kk*2+l8c)*16);
        ldmx2(bH[ni], rb);
        if (TERMS>=3) ldmx2(bL[ni], rb + MATB);
      }
      #pragma unroll
      for (int mi=0; mi<4; mi++)
        #pragma unroll
        for (int ni=0; ni<4; ni++){
          mma16816(acc[mi][ni], aH[mi], bH[ni]);
          if (TERMS>=3) mma16816(acc[mi][ni], aH[mi], bL[ni]);
          if (TERMS>=2) mma16816(acc[mi][ni], aL[mi], bH[ni]);
        }
    }
    __syncthreads();
    if (c+2 < nch) ldst(st, k0b + (c+2)*BK);
  }

  int rr = lane>>2, cc = (lane&3)*2;
  #pragma unroll
  for (int mi=0; mi<4; mi++){
    #pragma unroll
    for (int ni=0; ni<4; ni++){
      int r0 = m0 + wm*64 + mi*16 + rr;
      int c0 = n0 + wn*32 + ni*8 + cc;
      float* a = acc[mi][ni];
      if (MODE==0 || MODE==1){
        float* p0 = C + coff + (size_t)r0*ldc + c0;
        float* p1 = C + coff + (size_t)(r0+8)*ldc + c0;
        if (MODE==1){
          float2 o0 = *(float2*)p0, o1 = *(float2*)p1;
          a[0]+=o0.x; a[1]+=o0.y; a[2]+=o1.x; a[3]+=o1.y;
        }
        *(float2*)p0 = make_float2(a[0],a[1]);
        *(float2*)p1 = make_float2(a[2],a[3]);
      } else if (MODE==3){
        unsigned hp0 = ((unsigned)__bfloat16_as_ushort(__float2bfloat16(a[1]))<<16)
                     | __bfloat16_as_ushort(__float2bfloat16(a[0]));
        unsigned hp1 = ((unsigned)__bfloat16_as_ushort(__float2bfloat16(a[3]))<<16)
                     | __bfloat16_as_ushort(__float2bfloat16(a[2]));
        *(unsigned*)(Chi + coff + (size_t)r0*ldc + c0)     = hp0;
        *(unsigned*)(Chi + coff + (size_t)(r0+8)*ldc + c0) = hp1;
      } else {
        bf16 h0,l0,h1,l1,h2,l2,h3,l3;
        split2(a[0],h0,l0); split2(a[1],h1,l1);
        split2(a[2],h2,l2); split2(a[3],h3,l3);
        unsigned hp0 = ((unsigned)__bfloat16_as_ushort(h1)<<16) | __bfloat16_as_ushort(h0);
        unsigned lp0 = ((unsigned)__bfloat16_as_ushort(l1)<<16) | __bfloat16_as_ushort(l0);
        unsigned hp1 = ((unsigned)__bfloat16_as_ushort(h3)<<16) | __bfloat16_as_ushort(h2);
        unsigned lp1 = ((unsigned)__bfloat16_as_ushort(l3)<<16) | __bfloat16_as_ushort(l2);
        *(unsigned*)(Chi + coff + (size_t)r0*ldc + c0)     = hp0;
        *(unsigned*)(Clo + coff + (size_t)r0*ldc + c0)     = lp0;
        *(unsigned*)(Chi + coff + (size_t)(r0+8)*ldc + c0) = hp1;
        *(unsigned*)(Clo + coff + (size_t)(r0+8)*ldc + c0) = lp1;
      }
    }
  }
}

// ============ small SIMT kernels ============================================
__global__ void ln_embed(const int* __restrict__ x, const float* __restrict__ wte,
                         const float* __restrict__ g, float* __restrict__ dst){
  int r = blockIdx.x, t = threadIdx.x;
  const float* src = wte + (size_t)x[r]*D;
  float v0 = src[t], v1 = src[t+256];
  float mean = blockSum<8>(v0+v1) * (1.0f/D);
  float a0 = v0-mean, a1 = v1-mean;
  float var = blockSum<8>(a0*a0+a1*a1) * (1.0f/D);
  float inv = rsqrtf(var + 1e-5f);
  dst[(size_t)r*D + t]     = a0*inv*g[t];
  dst[(size_t)r*D + t+256] = a1*inv*g[t+256];
}
__global__ void ln_rows(const float* __restrict__ src0, const float* __restrict__ g,
                        float* __restrict__ dst){
  int r = blockIdx.x, t = threadIdx.x;
  const float* src = src0 + (size_t)r*D;
  float v0 = src[t], v1 = src[t+256];
  float mean = blockSum<8>(v0+v1) * (1.0f/D);
  float a0 = v0-mean, a1 = v1-mean;
  float var = blockSum<8>(a0*a0+a1*a1) * (1.0f/D);
  float inv = rsqrtf(var + 1e-5f);
  dst[(size_t)r*D + t]     = a0*inv*g[t];
  dst[(size_t)r*D + t+256] = a1*inv*g[t+256];
}
__global__ void ln_last(const float* __restrict__ g){
  int b = blockIdx.x, t = threadIdx.x;
  const float* src = d_fk + ((size_t)b*S + (S-1))*D;
  float v0 = src[t], v1 = src[t+256];
  float mean = blockSum<8>(v0+v1) * (1.0f/D);
  float a0 = v0-mean, a1 = v1-mean;
  float var = blockSum<8>(a0*a0+a1*a1) * (1.0f/D);
  float inv = rsqrtf(var + 1e-5f);
  d_lnlast[b*D + t]     = a0*inv*g[t];
  d_lnlast[b*D + t+256] = a1*inv*g[t+256];
}
__global__ void colmean_part(const float* __restrict__ wte){
  int g = blockIdx.x, t = threadIdx.x;
  const float* base = wte + (size_t)g*250*D + t;
  float acc = 0.f;
  for (int r=0; r<250; r++) acc += base[(size_t)r*D];
  d_mu_part[g*D + t] = acc;
}
__global__ void colmean_reduce(){
  int t = threadIdx.x;
  float acc = 0.f;
  for (int g=0; g<128; g++) acc += d_mu_part[g*D + t];
  d_mu[t] = acc * (1.0f/VOCAB);
}
__global__ void wtesplit(const float* __restrict__ wte){
  __shared__ float tile[32][33];
  int d0 = blockIdx.x*32, v0 = blockIdx.y*32;
  int x = threadIdx.x, y = threadIdx.y;
  #pragma unroll
  for (int i=0;i<32;i+=8){
    float val = wte[(size_t)(v0+y+i)*D + d0+x];
    tile[y+i][x] = val;
    bf16 hv, lv; split2(val, hv, lv);
    d_wh[(size_t)(v0+y+i)*D + d0+x] = hv;
    d_wl[(size_t)(v0+y+i)*D + d0+x] = lv;
  }
  __syncthreads();
  #pragma unroll
  for (int i=0;i<32;i+=8){
    float val = tile[x][y+i];
    bf16 hv, lv; split2(val, hv, lv);
    d_wth[(size_t)(d0+y+i)*VOCAB + v0+x] = hv;
    d_wtl[(size_t)(d0+y+i)*VOCAB + v0+x] = lv;
  }
}
__global__ void wqk_splitT(const float* __restrict__ W, bf16* __restrict__ th, bf16* __restrict__ tl){
  __shared__ float tile[32][33];
  int h = blockIdx.z;
  int d0 = blockIdx.x*32, e0 = blockIdx.y*32;
  const float* src = W + (size_t)h*D*D;
  bf16* oh = th + (size_t)h*D*D;
  bf16* ol = tl + (size_t)h*D*D;
  int x = threadIdx.x, y = threadIdx.y;
  #pragma unroll
  for (int i=0;i<32;i+=8)
    tile[y+i][x] = src[(size_t)(d0+y+i)*D + e0+x];
  __syncthreads();
  #pragma unroll
  for (int i=0;i<32;i+=8){
    float val = tile[x][y+i];
    bf16 hv, lv; split2(val, hv, lv);
    oh[(size_t)(e0+y+i)*D + d0+x] = hv;
    ol[(size_t)(e0+y+i)*D + d0+x] = lv;
  }
}
__global__ void psplit(){
  int i = blockIdx.x*256 + threadIdx.x;
  if (i < (S+1)*D) split2(d_p[i], d_ph[i], d_pl[i]);
}
__global__ void wosplit(const float* __restrict__ Wo){
  int i = blockIdx.x*256 + threadIdx.x;
  split2(Wo[i], d_woh[i], d_wol[i]);
}
__global__ void krnsplit(){
  int i = blockIdx.x*256 + threadIdx.x;
  split2(d_krn[i], d_krnh[i], d_krnl[i]);
}
// reduce WOK split-K partials of T@Wo^T, optionally accumulate into fk,
// and emit fk + split(fkh,fkl) in one pass (fksplit fused)
__global__ void wo_reduce(int accum){
  int i = blockIdx.x*256 + threadIdx.x;
  float a = 0.f;
  #pragma unroll
  for (int k=0;k<WOK;k++) a += d_part[(size_t)k*B*S*D + i];
  if (accum) a += d_fk[i];
  d_fk[i] = a;
  split2(a, d_fkh[i], d_fkl[i]);
}

__global__ void krn_softmax(){
  int s = blockIdx.x, h = blockIdx.y;
  float* row = d_krn + ((size_t)h*S + s)*S;
  const float scale = 0.044194173824159216f;
  int t0 = threadIdx.x, t1 = threadIdx.x + 256;
  float v0 = fminf(fmaxf(row[t0]*scale, -10.f), 10.f);
  float v1 = fminf(fmaxf(row[t1]*scale, -10.f), 10.f);
  bool ok0 = (t0 <= s), ok1 = (t1 <= s);
  float m0 = ok0 ? v0 : -1e30f;
  float m1 = ok1 ? v1 : -1e30f;
  float mx = blockMax<8>(fmaxf(m0, m1));
  float e0 = ok0 ? __expf(v0-mx) : 0.f;
  float e1 = ok1 ? __expf(v1-mx) : 0.f;
  float sum = blockSum<8>(e0+e1);
  float c = (1.0f/(1.0f+(float)s)) / sum;
  row[t0] = e0*c;
  row[t1] = e1*c;
}
__global__ void smax_pass1(){
  int b = blockIdx.y;
  int v = blockIdx.x*256 + threadIdx.x;
  const bf16* base = d_sch + (size_t)b*S*VOCAB + v;
  float m = -1e30f, sum = 0.f;
  #pragma unroll 4
  for (int s=0; s<S; s++){
    float x = __bfloat162float(base[(size_t)s*VOCAB]);
    float nm = fmaxf(m, x);
    sum = sum*__expf(m-nm) + __expf(x-nm);
    m = nm;
  }
  d_smax[b*VOCAB+v] = m;
  d_ssum[b*VOCAB+v] = sum;
}
__global__ void smax_pass2(){
  int b = blockIdx.y;
  int v = blockIdx.x*256 + threadIdx.x;
  const bf16* base = d_sch + (size_t)b*S*VOCAB + v;
  float m = d_smax[b*VOCAB+v];
  float inv = 1.f / d_ssum[b*VOCAB+v];
  bf16* ph = d_Rh + (size_t)b*S*VOCAB + v;
  #pragma unroll 4
  for (int s=0; s<S; s++){
    float e = __expf(__bfloat162float(base[(size_t)s*VOCAB]) - m) * inv;
    ph[(size_t)s*VOCAB] = __float2bfloat16(e);
  }
}
__global__ void rsumT(){
  int r = blockIdx.x;
  const bf16* ph = d_Rh + (size_t)r*VOCAB;
  float acc = 0.f;
  for (int v=threadIdx.x; v<VOCAB; v+=256)
    acc += __bfloat162float(ph[v]);
  acc = blockSum<8>(acc);
  if (threadIdx.x==0) d_Rsum[r] = acc;
}
__global__ void vmT(int mode){
  int i = blockIdx.x*256 + threadIdx.x;
  int b = i/(S*D); int rem = i%(S*D);
  int s = rem/D;   int dd = rem%D;
  float ex;
  if (mode){
    float num = 0.f;
    #pragma unroll
    for (int k=0;k<GSPLIT;k++) num += d_part[((size_t)(b*GSPLIT+k))*S*D + rem];
    ex = num / d_Rsum[b*S + s];
  } else {
    ex = d_mu[dd];
  }
  float v = d_e[i] - ex;
  bf16 hv, lv; split2(v, hv, lv);
  d_vmh[(size_t)b*D*S + (size_t)dd*S + s] = hv;
  d_vml[(size_t)b*D*S + (size_t)dd*S + s] = lv;
}
__global__ void logits_kernel(const float* __restrict__ wte, float* __restrict__ out){
  __shared__ float lnv[D];
  int b = blockIdx.x;
  for (int i=threadIdx.x; i<D; i+=256) lnv[i] = d_lnlast[b*D + i];
  __syncthreads();
  int w = threadIdx.x>>5, lane = threadIdx.x & 31;
  int v = blockIdx.y*8 + w;
  const float* wr = wte + (size_t)v*D;
  float acc = 0.f;
  #pragma unroll
  for (int j=lane; j<D; j+=32) acc += wr[j]*lnv[j];
  acc = warpSum(acc);
  if (lane==0) out[(size_t)b*VOCAB + v] = acc;
}

// ============ launch =========================================================
extern "C" void kernel_launch(void* const* d_in, const int* in_sizes, int n_in,
                              void* d_out, int out_size) {
  const int*   x   = (const int*)d_in[0];
  const float* wte = (const float*)d_in[1];
  const float* wpe = (const float*)d_in[2];
  const float* g_e = (const float*)d_in[3];
  const float* g_p = (const float*)d_in[4];
  const float* g_f = (const float*)d_in[5];
  const float* W_q = (const float*)d_in[6];
  const float* W_k = (const float*)d_in[7];
  const float* W_o = (const float*)d_in[8];
  float* out = (float*)d_out;

  cudaFuncSetAttribute(tgemm<0,3>, cudaFuncAttributeMaxDynamicSharedMemorySize, SME);
  cudaFuncSetAttribute(tgemm<2,3>, cudaFuncAttributeMaxDynamicSharedMemorySize, SME);
  cudaFuncSetAttribute(tgemm<3,2>, cudaFuncAttributeMaxDynamicSharedMemorySize, SME);
  cudaFuncSetAttribute(tgemm<0,1>, cudaFuncAttributeMaxDynamicSharedMemorySize, SME);

  float *de, *dp, *dkrn, *dfk, *dpart;
  bf16 *dph,*dpl,*dQh,*dQl,*dKh,*dKl,*dwqth,*dwqtl,*dwkth,*dwktl,*dsch;
  bf16 *dfkh,*dfkl,*dwh,*dwl,*dwth,*dwtl,*dwoh,*dwol,*dkrnh,*dkrnl,*dRh,*dvmh,*dvml,*dTh,*dTl;
  cudaGetSymbolAddress((void**)&de,   d_e);
  cudaGetSymbolAddress((void**)&dp,   d_p);
  cudaGetSymbolAddress((void**)&dph,  d_ph);
  cudaGetSymbolAddress((void**)&dpl,  d_pl);
  cudaGetSymbolAddress((void**)&dQh,  d_Qh);
  cudaGetSymbolAddress((void**)&dQl,  d_Ql);
  cudaGetSymbolAddress((void**)&dKh,  d_Kh);
  cudaGetSymbolAddress((void**)&dKl,  d_Kl);
  cudaGetSymbolAddress((void**)&dwqth,d_wqth);
  cudaGetSymbolAddress((void**)&dwqtl,d_wqtl);
  cudaGetSymbolAddress((void**)&dwkth,d_wkth);
  cudaGetSymbolAddress((void**)&dwktl,d_wktl);
  cudaGetSymbolAddress((void**)&dkrn, d_krn);
  cudaGetSymbolAddress((void**)&dfk,  d_fk);
  cudaGetSymbolAddress((void**)&dsch, d_sch);
  cudaGetSymbolAddress((void**)&dpart,d_part);
  cudaGetSymbolAddress((void**)&dfkh, d_fkh);
  cudaGetSymbolAddress((void**)&dfkl, d_fkl);
  cudaGetSymbolAddress((void**)&dwh,  d_wh);
  cudaGetSymbolAddress((void**)&dwl,  d_wl);
  cudaGetSymbolAddress((void**)&dwth, d_wth);
  cudaGetSymbolAddress((void**)&dwtl, d_wtl);
  cudaGetSymbolAddress((void**)&dwoh, d_woh);
  cudaGetSymbolAddress((void**)&dwol, d_wol);
  cudaGetSymbolAddress((void**)&dkrnh,d_krnh);
  cudaGetSymbolAddress((void**)&dkrnl,d_krnl);
  cudaGetSymbolAddress((void**)&dRh,  d_Rh);
  cudaGetSymbolAddress((void**)&dvmh, d_vmh);
  cudaGetSymbolAddress((void**)&dvml, d_vml);
  cudaGetSymbolAddress((void**)&dTh,  d_Th);
  cudaGetSymbolAddress((void**)&dTl,  d_Tl);

  // setup
  ln_embed<<<B*S, 256>>>(x, wte, g_e, de);
  ln_rows<<<S+1, 256>>>(wpe, g_p, dp);
  psplit<<<((S+1)*D+255)/256, 256>>>();
  colmean_part<<<128, 512>>>(wte);
  colmean_reduce<<<1, 512>>>();
  wtesplit<<<dim3(D/32, VOCAB/32), dim3(32,8)>>>(wte);
  wqk_splitT<<<dim3(D/32, D/32, H), dim3(32,8)>>>(W_q, dwqth, dwqtl);
  wqk_splitT<<<dim3(D/32, D/32, H), dim3(32,8)>>>(W_k, dwkth, dwktl);
  wosplit<<<(D*HD)/256, 256>>>(W_o);

  // Q = x_j @ W_q[h], K = x_i @ W_k[h]; outputs split bf16 (full precision)
  tgemm<2,3><<<dim3(4,4,H),256,SME>>>(dph+D,dpl+D,D,0,0, dwqth,dwqtl,D,0,(ll)D*D,
                                      0,dQh,dQl,D,0,(ll)S*D,0, D,H,1);
  tgemm<2,3><<<dim3(4,4,H),256,SME>>>(dph,dpl,D,0,0, dwkth,dwktl,D,0,(ll)D*D,
                                      0,dKh,dKl,D,0,(ll)S*D,0, D,H,1);
  // krn_raw = Q @ K^T (full precision)
  tgemm<0,3><<<dim3(4,4,H),256,SME>>>(dQh,dQl,D,0,(ll)S*D, dKh,dKl,D,0,(ll)S*D,
                                      dkrn,0,0,S,0,(ll)S*S,0, D,H,1);
  krn_softmax<<<dim3(S,H),256>>>();
  krnsplit<<<(H*S*S)/256, 256>>>();

  // layer 0: f_k = 0 -> ex = colmean(wte)
  vmT<<<(B*S*D)/256, 256>>>(0);
  tgemm<2,3><<<dim3(4,4,B*H),256,SME>>>(dkrnh,dkrnl,S,0,(ll)S*S,
                                        dvmh,dvml,S,(ll)D*S,0,
                                        0,dTh,dTl,HD,(ll)S*HD,(ll)D,0, S,H,1);
  tgemm<0,3><<<dim3(16,4,WOK),256,SME>>>(dTh,dTl,HD,0,0, dwoh,dwol,HD,0,0,
                                         dpart,0,0,D,0,0,(ll)B*S*D, HD,1,WOK);
  wo_reduce<<<(B*S*D)/256, 256>>>(0);

  for (int l=1; l<NLAYER; l++){
    // scoresT = fk @ wte^T : 2-term, stored bf16 (feeds softmax only)
    tgemm<3,2><<<dim3(4,250,B),256,SME>>>(dfkh,dfkl,D,(ll)S*D,0,
                                          dwh,dwl,D,0,0,
                                          0,dsch,dsch,VOCAB,(ll)S*VOCAB,0,0, D,1,1);
    smax_pass1<<<dim3(125,B),256>>>();
    smax_pass2<<<dim3(125,B),256>>>();
    rsumT<<<B*S, 256>>>();
    // num = R_hi @ wte : 1-term
    tgemm<0,1><<<dim3(4,4,B*GSPLIT),256,SME>>>(dRh,dRh,VOCAB,(ll)S*VOCAB,0,
                                               dwth,dwtl,VOCAB,0,0,
                                               dpart,0,0,D,(ll)GSPLIT*S*D,0,(ll)S*D,
                                               VOCAB,1,GSPLIT);
    vmT<<<(B*S*D)/256, 256>>>(1);
    tgemm<2,3><<<dim3(4,4,B*H),256,SME>>>(dkrnh,dkrnl,S,0,(ll)S*S,
                                          dvmh,dvml,S,(ll)D*S,0,
                                          0,dTh,dTl,HD,(ll)S*HD,(ll)D,0, S,H,1);
    tgemm<0,3><<<dim3(16,4,WOK),256,SME>>>(dTh,dTl,HD,0,0, dwoh,dwol,HD,0,0,
                                           dpart,0,0,D,0,0,(ll)B*S*D, HD,1,WOK);
    wo_reduce<<<(B*S*D)/256, 256>>>(1);
  }

  ln_last<<<B, 256>>>(g_f);
  logits_kernel<<<dim3(B, VOCAB/8), 256>>>(wte, out);
}